// round 11
// baseline (speedup 1.0000x reference)
#include <cuda_runtime.h>
#include <math.h>
#include <stdint.h>

#define MAXN 50048
#define MAXE 600064

// ---------------- scratch (static device globals; no allocation) ----------------
__device__ float g_b1[(size_t)MAXN * 128];
__device__ float g_Q [(size_t)MAXN * 128];
__device__ float g_K [(size_t)MAXN * 128];
__device__ float g_V [(size_t)MAXN * 128];
__device__ float g_x [(size_t)MAXN * 128];
__device__ float g_wV[(size_t)MAXN * 128];
__device__ float g_z [(size_t)MAXN * 4];
__device__ float g_t [(size_t)MAXN * 256];   // FFN hidden; later reused as ener buffer

__device__ __forceinline__ float clip5(float x) { return fminf(fmaxf(x, -5.f), 5.f); }
__device__ __forceinline__ float sigm(float x)  { return 1.f / (1.f + expf(-x)); }

__device__ __forceinline__ void red_add_v4(float* p, float a, float b, float c, float d) {
    asm volatile("red.global.add.v4.f32 [%0], {%1,%2,%3,%4};"
                 :: "l"(p), "f"(a), "f"(b), "f"(c), "f"(d) : "memory");
}
__device__ __forceinline__ void red_add_f(float* p, float v) {
    asm volatile("red.global.add.f32 [%0], %1;" :: "l"(p), "f"(v) : "memory");
}

// ---- TF32 helpers ----
__device__ __forceinline__ void tf32split(float x, uint32_t& hi, uint32_t& lo) {
    uint32_t h; asm("cvt.rna.tf32.f32 %0, %1;" : "=r"(h) : "f"(x));
    float hf = __uint_as_float(h);
    float l = x - hf;
    uint32_t lr; asm("cvt.rna.tf32.f32 %0, %1;" : "=r"(lr) : "f"(l));
    hi = h; lo = lr;
}
__device__ __forceinline__ float tf32r(float x) {
    uint32_t h; asm("cvt.rna.tf32.f32 %0, %1;" : "=r"(h) : "f"(x));
    return __uint_as_float(h);
}
__device__ __forceinline__ void mma8(float* d, const uint32_t* a, uint32_t b0, uint32_t b1) {
    asm volatile("mma.sync.aligned.m16n8k8.row.col.f32.tf32.tf32.f32 "
        "{%0,%1,%2,%3}, {%4,%5,%6,%7}, {%8,%9}, {%0,%1,%2,%3};"
        : "+f"(d[0]), "+f"(d[1]), "+f"(d[2]), "+f"(d[3])
        : "r"(a[0]), "r"(a[1]), "r"(a[2]), "r"(a[3]), "r"(b0), "r"(b1));
}

// ---------------- zero fill (wV and z in ONE launch) ----------------
__global__ void fzero2_kernel(float4* __restrict__ wv, float4* __restrict__ z,
                              int nwv4, int nz4) {
    int i = blockIdx.x * blockDim.x + threadIdx.x;
    if (i < nwv4) wv[i] = make_float4(0.f, 0.f, 0.f, 0.f);
    else {
        int j = i - nwv4;
        if (j < nz4) z[j] = make_float4(0.f, 0.f, 0.f, 0.f);
    }
}

// ---------------- row LayerNorm (warp per 128-wide row) ----------------
__global__ void ln_kernel(const float* __restrict__ in, float* __restrict__ out,
                          const float* __restrict__ w, const float* __restrict__ b, int rows) {
    int warp = (blockIdx.x * blockDim.x + threadIdx.x) >> 5;
    int lane = threadIdx.x & 31;
    if (warp >= rows) return;
    float4 v = *(const float4*)(in + (size_t)warp * 128 + 4 * lane);
    float s  = v.x + v.y + v.z + v.w;
    float sq = v.x * v.x + v.y * v.y + v.z * v.z + v.w * v.w;
#pragma unroll
    for (int o = 16; o; o >>= 1) {
        s  += __shfl_xor_sync(0xffffffffu, s,  o);
        sq += __shfl_xor_sync(0xffffffffu, sq, o);
    }
    float mu   = s * (1.f / 128.f);
    float rstd = rsqrtf(sq * (1.f / 128.f) - mu * mu + 1e-5f);
    float4 wv = *(const float4*)(w + 4 * lane);
    float4 bv = *(const float4*)(b + 4 * lane);
    float4 o4;
    o4.x = (v.x - mu) * rstd * wv.x + bv.x;
    o4.y = (v.y - mu) * rstd * wv.y + bv.y;
    o4.z = (v.z - mu) * rstd * wv.z + bv.z;
    o4.w = (v.w - mu) * rstd * wv.w + bv.w;
    *(float4*)(out + (size_t)warp * 128 + 4 * lane) = o4;
}

// ---------------- tensor-core GEMM body (R6-proven): 128x128, 3xTF32 ------------------
#define AS 36
#define WS 136
template <int EPI>
__device__ __forceinline__ void gemm_body(
    const float* __restrict__ A, const float* __restrict__ W,
    const float* __restrict__ bias, const float* __restrict__ res,
    float* __restrict__ C, int M, int K, int NC, int row0, int cb,
    float* A_sh, float* Whi, float* Wlo) {
    int tid = threadIdx.x;
    int lane = tid & 31, wid = tid >> 5;
    int wm = wid >> 1, wn = wid & 1;
    int g = lane >> 2, t = lane & 3;
    float acc[2][8][4];
#pragma unroll
    for (int mf = 0; mf < 2; mf++)
#pragma unroll
        for (int nf = 0; nf < 8; nf++)
#pragma unroll
            for (int u = 0; u < 4; u++) acc[mf][nf][u] = 0.f;

    int nkt = K >> 5;
    for (int kt = 0; kt < nkt; ++kt) {
#pragma unroll
        for (int it = 0; it < 4; ++it) {
            int idx = tid + it * 256;
            int r = idx >> 3, c4 = (idx & 7) << 2;
            float4 v = make_float4(0.f, 0.f, 0.f, 0.f);
            if (row0 + r < M) v = *(const float4*)(A + (size_t)(row0 + r) * K + kt * 32 + c4);
            *(float4*)(A_sh + r * AS + c4) = v;
        }
#pragma unroll
        for (int it = 0; it < 4; ++it) {
            int idx = tid + it * 256;
            int kk = idx >> 5, wc = (idx & 31) << 2;
            float4 v = *(const float4*)(W + (size_t)(kt * 32 + kk) * NC + cb + wc);
            uint32_t h, l; float4 hv, lv;
            tf32split(v.x, h, l); hv.x = __uint_as_float(h); lv.x = __uint_as_float(l);
            tf32split(v.y, h, l); hv.y = __uint_as_float(h); lv.y = __uint_as_float(l);
            tf32split(v.z, h, l); hv.z = __uint_as_float(h); lv.z = __uint_as_float(l);
            tf32split(v.w, h, l); hv.w = __uint_as_float(h); lv.w = __uint_as_float(l);
            *(float4*)(Whi + kk * WS + wc) = hv;
            *(float4*)(Wlo + kk * WS + wc) = lv;
        }
        __syncthreads();
#pragma unroll
        for (int k8 = 0; k8 < 4; ++k8) {
            int ck = k8 * 8;
            uint32_t ahi[2][4], alo[2][4];
#pragma unroll
            for (int mf = 0; mf < 2; ++mf) {
                int rb = 32 * wm + 16 * mf;
                float a0 = A_sh[(rb + g)     * AS + ck + t];
                float a1 = A_sh[(rb + g + 8) * AS + ck + t];
                float a2 = A_sh[(rb + g)     * AS + ck + t + 4];
                float a3 = A_sh[(rb + g + 8) * AS + ck + t + 4];
                tf32split(a0, ahi[mf][0], alo[mf][0]);
                tf32split(a1, ahi[mf][1], alo[mf][1]);
                tf32split(a2, ahi[mf][2], alo[mf][2]);
                tf32split(a3, ahi[mf][3], alo[mf][3]);
            }
#pragma unroll
            for (int nf = 0; nf < 8; ++nf) {
                int nb = 64 * wn + 8 * nf + g;
                uint32_t bh0 = __float_as_uint(Whi[(ck + t)     * WS + nb]);
                uint32_t bh1 = __float_as_uint(Whi[(ck + t + 4) * WS + nb]);
                uint32_t bl0 = __float_as_uint(Wlo[(ck + t)     * WS + nb]);
                uint32_t bl1 = __float_as_uint(Wlo[(ck + t + 4) * WS + nb]);
#pragma unroll
                for (int mf = 0; mf < 2; ++mf) {
                    mma8(acc[mf][nf], alo[mf], bh0, bh1);
                    mma8(acc[mf][nf], ahi[mf], bl0, bl1);
                    mma8(acc[mf][nf], ahi[mf], bh0, bh1);
                }
            }
        }
        __syncthreads();
    }
#pragma unroll
    for (int mf = 0; mf < 2; ++mf) {
#pragma unroll
        for (int nf = 0; nf < 8; ++nf) {
            int c  = cb + 64 * wn + 8 * nf + 2 * t;
            int r0 = row0 + 32 * wm + 16 * mf + g;
            float2 v0 = make_float2(acc[mf][nf][0], acc[mf][nf][1]);
            float2 v1 = make_float2(acc[mf][nf][2], acc[mf][nf][3]);
            if (EPI == 2) {
                v0.x = v0.x / (1.f + expf(-v0.x)); v0.y = v0.y / (1.f + expf(-v0.y));
                v1.x = v1.x / (1.f + expf(-v1.x)); v1.y = v1.y / (1.f + expf(-v1.y));
            }
            if (r0 < M) {
                if (EPI == 1) {
                    float2 b = *(const float2*)(bias + c);
                    float2 rr = *(const float2*)(res + (size_t)r0 * NC + c);
                    v0.x += b.x + rr.x; v0.y += b.y + rr.y;
                }
                if (EPI == 3) {
                    float2 rr = *(const float2*)(res + (size_t)r0 * NC + c);
                    v0.x += rr.x; v0.y += rr.y;
                }
                *(float2*)(C + (size_t)r0 * NC + c) = v0;
            }
            int r1 = r0 + 8;
            if (r1 < M) {
                if (EPI == 1) {
                    float2 b = *(const float2*)(bias + c);
                    float2 rr = *(const float2*)(res + (size_t)r1 * NC + c);
                    v1.x += b.x + rr.x; v1.y += b.y + rr.y;
                }
                if (EPI == 3) {
                    float2 rr = *(const float2*)(res + (size_t)r1 * NC + c);
                    v1.x += rr.x; v1.y += rr.y;
                }
                *(float2*)(C + (size_t)r1 * NC + c) = v1;
            }
        }
    }
}

#define GEMM_SMEM ((128 * AS + 2 * 32 * WS) * 4)

template <int EPI>
__global__ void __launch_bounds__(256, 2) gemm_kernel(
    const float* __restrict__ A, const float* __restrict__ W,
    const float* __restrict__ bias, const float* __restrict__ res,
    float* __restrict__ C, int M, int K, int NC) {
    extern __shared__ float gsh[];
    float* A_sh = gsh;
    float* Whi  = gsh + 128 * AS;
    float* Wlo  = Whi + 32 * WS;
    gemm_body<EPI>(A, W, bias, res, C, M, K, NC, blockIdx.x * 128, blockIdx.y * 128,
                   A_sh, Whi, Wlo);
}

__global__ void __launch_bounds__(256, 2) qkv_kernel(
    const float* __restrict__ A,
    const float* __restrict__ Wq, const float* __restrict__ Wk, const float* __restrict__ Wv,
    float* __restrict__ Q, float* __restrict__ Ko, float* __restrict__ V, int M) {
    extern __shared__ float gsh[];
    float* A_sh = gsh;
    float* Whi  = gsh + 128 * AS;
    float* Wlo  = Whi + 32 * WS;
    const float* W = (blockIdx.y == 0) ? Wq : (blockIdx.y == 1) ? Wk : Wv;
    float* C       = (blockIdx.y == 0) ? Q  : (blockIdx.y == 1) ? Ko : V;
    gemm_body<0>(A, W, nullptr, nullptr, C, M, 128, 128, blockIdx.x * 128, 0, A_sh, Whi, Wlo);
}

// ---------------- fused edge kernel: LN -> Pe GEMM (2xTF32) -> score/exp -> scatter ----
// LN values stored PRE-ROUNDED to tf32 (A-lo plane dropped: 2-term MMA).
#define LN_STRIDE 132
__global__ void __launch_bounds__(256, 2) edge_kernel(
    const float* __restrict__ ef, const float* __restrict__ lnw, const float* __restrict__ lnb,
    const float* __restrict__ We, const int* __restrict__ src, const int* __restrict__ dst,
    const float* __restrict__ Q, const float* __restrict__ Kv, const float* __restrict__ V,
    float* __restrict__ wV, float* __restrict__ z, int E) {
    extern __shared__ float sh[];
    float* LN_sh = sh;                           // [128][132] tf32-rounded LN, later Pe
    float* Whi   = sh + 128 * LN_STRIDE;         // [32][136]
    float* Wlo   = Whi + 32 * WS;                // [32][136]
    int* s_sh = (int*)(Wlo + 32 * WS);           // [128]
    int* d_sh = s_sh + 128;                      // [128]

    int tid = threadIdx.x, lane = tid & 31, w = tid >> 5;
    int e0 = blockIdx.x * 128;
    if (tid < 128) {
        int e = e0 + tid;
        s_sh[tid] = (e < E) ? src[e] : 0;
        d_sh[tid] = (e < E) ? dst[e] : 0;
    }
    float4 lw = *(const float4*)(lnw + 4 * lane);
    float4 lb = *(const float4*)(lnb + 4 * lane);
    // phase A: LN, stored tf32-rounded
#pragma unroll
    for (int i = 0; i < 16; i++) {
        int r = w * 16 + i;
        int e = e0 + r;
        float4 v = make_float4(0.f, 0.f, 0.f, 0.f);
        if (e < E) v = *(const float4*)(ef + (size_t)e * 128 + 4 * lane);
        float s  = v.x + v.y + v.z + v.w;
        float sq = v.x * v.x + v.y * v.y + v.z * v.z + v.w * v.w;
#pragma unroll
        for (int o = 16; o; o >>= 1) {
            s  += __shfl_xor_sync(0xffffffffu, s,  o);
            sq += __shfl_xor_sync(0xffffffffu, sq, o);
        }
        float mu   = s * (1.f / 128.f);
        float rstd = rsqrtf(sq * (1.f / 128.f) - mu * mu + 1e-5f);
        float4 o4;
        o4.x = tf32r((v.x - mu) * rstd * lw.x + lb.x);
        o4.y = tf32r((v.y - mu) * rstd * lw.y + lb.y);
        o4.z = tf32r((v.z - mu) * rstd * lw.z + lb.z);
        o4.w = tf32r((v.w - mu) * rstd * lw.w + lb.w);
        *(float4*)(LN_sh + r * LN_STRIDE + 4 * lane) = o4;
    }
    __syncthreads();
    // phase B: Pe = LN @ We via 2xTF32 (A single tf32 plane, B hi+lo)
    int wm = w >> 1, wn = w & 1;
    int g = lane >> 2, t = lane & 3;
    float acc[2][8][4];
#pragma unroll
    for (int mf = 0; mf < 2; mf++)
#pragma unroll
        for (int nf = 0; nf < 8; nf++)
#pragma unroll
            for (int u = 0; u < 4; u++) acc[mf][nf][u] = 0.f;
    for (int kt = 0; kt < 4; ++kt) {
#pragma unroll
        for (int it = 0; it < 4; ++it) {
            int idx = tid + it * 256;
            int kk = idx >> 5, wc = (idx & 31) << 2;
            float4 v = *(const float4*)(We + (size_t)(kt * 32 + kk) * 128 + wc);
            uint32_t h, l; float4 hv, lv;
            tf32split(v.x, h, l); hv.x = __uint_as_float(h); lv.x = __uint_as_float(l);
            tf32split(v.y, h, l); hv.y = __uint_as_float(h); lv.y = __uint_as_float(l);
            tf32split(v.z, h, l); hv.z = __uint_as_float(h); lv.z = __uint_as_float(l);
            tf32split(v.w, h, l); hv.w = __uint_as_float(h); lv.w = __uint_as_float(l);
            *(float4*)(Whi + kk * WS + wc) = hv;
            *(float4*)(Wlo + kk * WS + wc) = lv;
        }
        __syncthreads();
#pragma unroll
        for (int k8 = 0; k8 < 4; ++k8) {
            int ckA = kt * 32 + k8 * 8;
            int ckW = k8 * 8;
            uint32_t a[2][4];
#pragma unroll
            for (int mf = 0; mf < 2; ++mf) {
                int rb = 32 * wm + 16 * mf;
                a[mf][0] = __float_as_uint(LN_sh[(rb + g)     * LN_STRIDE + ckA + t]);
                a[mf][1] = __float_as_uint(LN_sh[(rb + g + 8) * LN_STRIDE + ckA + t]);
                a[mf][2] = __float_as_uint(LN_sh[(rb + g)     * LN_STRIDE + ckA + t + 4]);
                a[mf][3] = __float_as_uint(LN_sh[(rb + g + 8) * LN_STRIDE + ckA + t + 4]);
            }
#pragma unroll
            for (int nf = 0; nf < 8; ++nf) {
                int nb = 64 * wn + 8 * nf + g;
                uint32_t bh0 = __float_as_uint(Whi[(ckW + t)     * WS + nb]);
                uint32_t bh1 = __float_as_uint(Whi[(ckW + t + 4) * WS + nb]);
                uint32_t bl0 = __float_as_uint(Wlo[(ckW + t)     * WS + nb]);
                uint32_t bl1 = __float_as_uint(Wlo[(ckW + t + 4) * WS + nb]);
#pragma unroll
                for (int mf = 0; mf < 2; ++mf) {
                    mma8(acc[mf][nf], a[mf], bl0, bl1);
                    mma8(acc[mf][nf], a[mf], bh0, bh1);
                }
            }
        }
        __syncthreads();
    }
    // stash Pe into LN_sh
#pragma unroll
    for (int mf = 0; mf < 2; ++mf) {
#pragma unroll
        for (int nf = 0; nf < 8; ++nf) {
            int r0 = 32 * wm + 16 * mf + g;
            int c  = 64 * wn + 8 * nf + 2 * t;
            *(float2*)(LN_sh + r0 * LN_STRIDE + c)       = make_float2(acc[mf][nf][0], acc[mf][nf][1]);
            *(float2*)(LN_sh + (r0 + 8) * LN_STRIDE + c) = make_float2(acc[mf][nf][2], acc[mf][nf][3]);
        }
    }
    __syncthreads();
    // phase C: per-edge score, exp, scatter (16 edges per warp, prefetched)
    const float inv = 0.17677669529663687f;
    int head = lane >> 3;
    int base = w * 16;
    int si = s_sh[base], di = d_sh[base];
    float4 kq = *(const float4*)(Kv + (size_t)si * 128 + 4 * lane);
    float4 qv = *(const float4*)(Q  + (size_t)di * 128 + 4 * lane);
    float4 vv = *(const float4*)(V  + (size_t)si * 128 + 4 * lane);
#pragma unroll
    for (int j = 0; j < 16; j++) {
        int e = e0 + base + j;
        float4 kqc = kq, qvc = qv, vvc = vv;
        int dic = di;
        if (j < 15) {
            int sn = s_sh[base + j + 1], dn = d_sh[base + j + 1];
            kq = *(const float4*)(Kv + (size_t)sn * 128 + 4 * lane);
            qv = *(const float4*)(Q  + (size_t)dn * 128 + 4 * lane);
            vv = *(const float4*)(V  + (size_t)sn * 128 + 4 * lane);
            di = dn;
        }
        if (e < E) {
            float4 pe = *(float4*)(LN_sh + (base + j) * LN_STRIDE + 4 * lane);
            float tt = clip5(kqc.x * qvc.x * inv) * pe.x + clip5(kqc.y * qvc.y * inv) * pe.y
                     + clip5(kqc.z * qvc.z * inv) * pe.z + clip5(kqc.w * qvc.w * inv) * pe.w;
            tt += __shfl_xor_sync(0xffffffffu, tt, 1);
            tt += __shfl_xor_sync(0xffffffffu, tt, 2);
            tt += __shfl_xor_sync(0xffffffffu, tt, 4);
            float s = expf(clip5(tt));
            float* dp = wV + (size_t)dic * 128 + 4 * lane;
            red_add_v4(dp, vvc.x * s, vvc.y * s, vvc.z * s, vvc.w * s);
            if ((lane & 7) == 0) red_add_f(z + (size_t)dic * 4 + head, s);
        }
    }
}
#define EDGE_SMEM ((128 * LN_STRIDE + 2 * 32 * WS) * 4 + 2 * 128 * 4)

// ---------------- attn = wV / (z + 1e-6) ----------------
__global__ void attn_kernel(const float* __restrict__ wV, const float* __restrict__ z,
                            float* __restrict__ outp, int N) {
    int i = blockIdx.x * blockDim.x + threadIdx.x;
    if (i >= N * 32) return;
    int n = i >> 5;
    int head = (i & 31) >> 3;
    float invz = 1.f / (z[(size_t)n * 4 + head] + 1e-6f);
    float4 v = *(const float4*)(wV + (size_t)i * 4);
    v.x *= invz; v.y *= invz; v.z *= invz; v.w *= invz;
    *(float4*)(outp + (size_t)i * 4) = v;
}

// ---------------- Set2Set: one block per graph, all 3 iterations internal ----------------
__global__ void __launch_bounds__(256) set2set_kernel(
    const float* __restrict__ nf, const int* __restrict__ gid,
    const float* __restrict__ W_ih, const float* __restrict__ W_hh,
    const float* __restrict__ b_ih, const float* __restrict__ b_hh,
    float* __restrict__ ener, float* __restrict__ out, int N) {
    __shared__ float qs[256], hh[128], cc[128], gates[512], rsh[8 * 128], red[16];
    int tid = threadIdx.x, lane = tid & 31, w = tid >> 5;
    int g = blockIdx.x;
    int lo, hi;
    {
        int a = 0, b = N;
        while (a < b) { int m = (a + b) >> 1; if (gid[m] < g) a = m + 1; else b = m; }
        lo = a;
        b = N;
        while (a < b) { int m = (a + b) >> 1; if (gid[m] < g + 1) a = m + 1; else b = m; }
        hi = a;
    }
    qs[tid] = 0.f;
    if (tid < 128) { hh[tid] = 0.f; cc[tid] = 0.f; }
    __syncthreads();

    for (int it = 0; it < 3; ++it) {
        for (int j = tid; j < 512; j += 256) {
            float acc = b_ih[j] + b_hh[j];
            const float* wi = W_ih + (size_t)j * 256;
#pragma unroll 8
            for (int k2 = 0; k2 < 256; k2++) acc += qs[k2] * wi[k2];
            const float* whp = W_hh + (size_t)j * 128;
#pragma unroll 8
            for (int k2 = 0; k2 < 128; k2++) acc += hh[k2] * whp[k2];
            gates[j] = acc;
        }
        __syncthreads();
        if (tid < 128) {
            float c = sigm(gates[128 + tid]) * cc[tid] + sigm(gates[tid]) * tanhf(gates[256 + tid]);
            cc[tid] = c;
            hh[tid] = sigm(gates[384 + tid]) * tanhf(c);
        }
        __syncthreads();
        float mloc = -INFINITY;
        float4 h4 = *(float4*)&hh[4 * lane];
        for (int n = lo + w; n < hi; n += 8) {
            float4 a4 = *(const float4*)(nf + (size_t)n * 128 + 4 * lane);
            float t = a4.x * h4.x + a4.y * h4.y + a4.z * h4.z + a4.w * h4.w;
#pragma unroll
            for (int o = 16; o; o >>= 1) t += __shfl_xor_sync(0xffffffffu, t, o);
            if (lane == 0) ener[n] = t;
            mloc = fmaxf(mloc, t);
        }
#pragma unroll
        for (int o = 16; o; o >>= 1) mloc = fmaxf(mloc, __shfl_xor_sync(0xffffffffu, mloc, o));
        if (lane == 0) red[w] = mloc;
        __syncthreads();
        if (tid == 0) {
            float m = -INFINITY;
            for (int i = 0; i < 8; i++) m = fmaxf(m, red[i]);
            red[8] = m;
        }
        __syncthreads();
        float m = red[8];
        float dloc = 0.f;
        for (int n = lo + tid; n < hi; n += 256) dloc += expf(ener[n] - m);
#pragma unroll
        for (int o = 16; o; o >>= 1) dloc += __shfl_xor_sync(0xffffffffu, dloc, o);
        __syncthreads();
        if (lane == 0) red[w] = dloc;
        __syncthreads();
        if (tid == 0) {
            float d = 0.f;
            for (int i = 0; i < 8; i++) d += red[i];
            red[9] = d;
        }
        __syncthreads();
        float invd = 1.f / red[9];
        float4 racc = make_float4(0.f, 0.f, 0.f, 0.f);
        for (int n = lo + w; n < hi; n += 8) {
            float coef = expf(ener[n] - m) * invd;
            float4 a4 = *(const float4*)(nf + (size_t)n * 128 + 4 * lane);
            racc.x += coef * a4.x; racc.y += coef * a4.y;
            racc.z += coef * a4.z; racc.w += coef * a4.w;
        }
        *(float4*)&rsh[w * 128 + 4 * lane] = racc;
        __syncthreads();
        if (tid < 128) {
            float ro = 0.f;
#pragma unroll
            for (int i = 0; i < 8; i++) ro += rsh[i * 128 + tid];
            qs[tid] = hh[tid];
            qs[128 + tid] = ro;
        }
        __syncthreads();
    }
    out[(size_t)g * 256 + tid] = qs[tid];
}

// ---------------- launch ----------------
extern "C" void kernel_launch(void* const* d_in, const int* in_sizes, int n_in,
                              void* d_out, int out_size) {
    const float* node = (const float*)d_in[0];
    const float* edge = (const float*)d_in[1];
    const float* Wq = (const float*)d_in[2];
    const float* Wk = (const float*)d_in[3];
    const float* Wv = (const float*)d_in[4];
    const float* We = (const float*)d_in[5];
    const float* Wo = (const float*)d_in[6];
    const float* bo = (const float*)d_in[7];
    const float* W1 = (const float*)d_in[8];
    const float* W2 = (const float*)d_in[9];
    const float* l1nw = (const float*)d_in[10];
    const float* l1nb = (const float*)d_in[11];
    const float* l1ew = (const float*)d_in[12];
    const float* l1eb = (const float*)d_in[13];
    const float* l2w = (const float*)d_in[14];
    const float* l2b = (const float*)d_in[15];
    const float* Wih = (const float*)d_in[16];
    const float* Whh = (const float*)d_in[17];
    const float* bih = (const float*)d_in[18];
    const float* bhh = (const float*)d_in[19];
    const int* src = (const int*)d_in[20];
    const int* dst = (const int*)d_in[21];
    const int* gid = (const int*)d_in[22];

    int N = in_sizes[0] / 128;
    int E = in_sizes[20];
    int G = out_size / 256;

    float *b1, *q, *k, *v, *x, *wv, *z, *t;
    cudaGetSymbolAddress((void**)&b1, g_b1);
    cudaGetSymbolAddress((void**)&q,  g_Q);
    cudaGetSymbolAddress((void**)&k,  g_K);
    cudaGetSymbolAddress((void**)&v,  g_V);
    cudaGetSymbolAddress((void**)&x,  g_x);
    cudaGetSymbolAddress((void**)&wv, g_wV);
    cudaGetSymbolAddress((void**)&z,  g_z);
    cudaGetSymbolAddress((void**)&t,  g_t);

    cudaFuncSetAttribute(edge_kernel, cudaFuncAttributeMaxDynamicSharedMemorySize, EDGE_SMEM);
    cudaFuncSetAttribute(qkv_kernel, cudaFuncAttributeMaxDynamicSharedMemorySize, GEMM_SMEM);
    cudaFuncSetAttribute(gemm_kernel<1>, cudaFuncAttributeMaxDynamicSharedMemorySize, GEMM_SMEM);
    cudaFuncSetAttribute(gemm_kernel<2>, cudaFuncAttributeMaxDynamicSharedMemorySize, GEMM_SMEM);
    cudaFuncSetAttribute(gemm_kernel<3>, cudaFuncAttributeMaxDynamicSharedMemorySize, GEMM_SMEM);

    int gnodes = (N + 127) / 128;

    ln_kernel<<<(N + 7) / 8, 256>>>(node, b1, l1nw, l1nb, N);
    qkv_kernel<<<dim3(gnodes, 3), 256, GEMM_SMEM>>>(b1, Wq, Wk, Wv, q, k, v, N);
    fzero2_kernel<<<(N * 33 + 255) / 256, 256>>>((float4*)wv, (float4*)z, N * 32, N);
    edge_kernel<<<(E + 127) / 128, 256, EDGE_SMEM>>>(edge, l1ew, l1eb, We, src, dst,
                                                     q, k, v, wv, z, E);
    attn_kernel<<<(N * 32 + 255) / 256, 256>>>(wv, z, b1, N);
    gemm_kernel<1><<<dim3(gnodes, 1), 256, GEMM_SMEM>>>(b1, Wo, bo, node, x, N, 128, 128);
    ln_kernel<<<(N + 7) / 8, 256>>>(x, q, l2w, l2b, N);
    gemm_kernel<2><<<dim3(gnodes, 2), 256, GEMM_SMEM>>>(q, W1, nullptr, nullptr, t, N, 128, 256);
    gemm_kernel<3><<<dim3(gnodes, 1), 256, GEMM_SMEM>>>(t, W2, nullptr, x, k, N, 256, 128);
    set2set_kernel<<<G, 256>>>(k, gid, Wih, Whh, bih, bhh, t, (float*)d_out, N);
}

// round 12
// speedup vs baseline: 1.4032x; 1.4032x over previous
#include <cuda_runtime.h>
#include <math.h>
#include <stdint.h>

#define MAXN 50048
#define MAXE 600064

// ---------------- scratch (static device globals; no allocation) ----------------
__device__ float g_b1[(size_t)MAXN * 128];
__device__ float g_Q [(size_t)MAXN * 128];
__device__ float g_K [(size_t)MAXN * 128];
__device__ float g_V [(size_t)MAXN * 128];
__device__ float g_x [(size_t)MAXN * 128];
__device__ float g_wV[(size_t)MAXN * 128];
__device__ float g_z [(size_t)MAXN * 4];
__device__ float g_t [(size_t)MAXN * 256];
__device__ float g_en[(size_t)MAXN];

__device__ __forceinline__ float clip5(float x) { return fminf(fmaxf(x, -5.f), 5.f); }
__device__ __forceinline__ float sigm(float x)  { return 1.f / (1.f + expf(-x)); }

__device__ __forceinline__ void red_add_v4(float* p, float a, float b, float c, float d) {
    asm volatile("red.global.add.v4.f32 [%0], {%1,%2,%3,%4};"
                 :: "l"(p), "f"(a), "f"(b), "f"(c), "f"(d) : "memory");
}
__device__ __forceinline__ void red_add_f(float* p, float v) {
    asm volatile("red.global.add.f32 [%0], %1;" :: "l"(p), "f"(v) : "memory");
}

// ---- 3xTF32 helpers ----
__device__ __forceinline__ void tf32split(float x, uint32_t& hi, uint32_t& lo) {
    uint32_t h; asm("cvt.rna.tf32.f32 %0, %1;" : "=r"(h) : "f"(x));
    float hf = __uint_as_float(h);
    float l = x - hf;
    uint32_t lr; asm("cvt.rna.tf32.f32 %0, %1;" : "=r"(lr) : "f"(l));
    hi = h; lo = lr;
}
__device__ __forceinline__ void mma8(float* d, const uint32_t* a, uint32_t b0, uint32_t b1) {
    asm volatile("mma.sync.aligned.m16n8k8.row.col.f32.tf32.tf32.f32 "
        "{%0,%1,%2,%3}, {%4,%5,%6,%7}, {%8,%9}, {%0,%1,%2,%3};"
        : "+f"(d[0]), "+f"(d[1]), "+f"(d[2]), "+f"(d[3])
        : "r"(a[0]), "r"(a[1]), "r"(a[2]), "r"(a[3]), "r"(b0), "r"(b1));
}

// ---------------- zero fill (wV and z in ONE launch) ----------------
__global__ void fzero2_kernel(float4* __restrict__ wv, float4* __restrict__ z,
                              int nwv4, int nz4) {
    int i = blockIdx.x * blockDim.x + threadIdx.x;
    if (i < nwv4) wv[i] = make_float4(0.f, 0.f, 0.f, 0.f);
    else {
        int j = i - nwv4;
        if (j < nz4) z[j] = make_float4(0.f, 0.f, 0.f, 0.f);
    }
}

// ---------------- row LayerNorm (warp per 128-wide row) ----------------
__global__ void ln_kernel(const float* __restrict__ in, float* __restrict__ out,
                          const float* __restrict__ w, const float* __restrict__ b, int rows) {
    int warp = (blockIdx.x * blockDim.x + threadIdx.x) >> 5;
    int lane = threadIdx.x & 31;
    if (warp >= rows) return;
    float4 v = *(const float4*)(in + (size_t)warp * 128 + 4 * lane);
    float s  = v.x + v.y + v.z + v.w;
    float sq = v.x * v.x + v.y * v.y + v.z * v.z + v.w * v.w;
#pragma unroll
    for (int o = 16; o; o >>= 1) {
        s  += __shfl_xor_sync(0xffffffffu, s,  o);
        sq += __shfl_xor_sync(0xffffffffu, sq, o);
    }
    float mu   = s * (1.f / 128.f);
    float rstd = rsqrtf(sq * (1.f / 128.f) - mu * mu + 1e-5f);
    float4 wv = *(const float4*)(w + 4 * lane);
    float4 bv = *(const float4*)(b + 4 * lane);
    float4 o4;
    o4.x = (v.x - mu) * rstd * wv.x + bv.x;
    o4.y = (v.y - mu) * rstd * wv.y + bv.y;
    o4.z = (v.z - mu) * rstd * wv.z + bv.z;
    o4.w = (v.w - mu) * rstd * wv.w + bv.w;
    *(float4*)(out + (size_t)warp * 128 + 4 * lane) = o4;
}

// ---------------- tensor-core GEMM body (R6-proven): 128x128, 3xTF32 ------------------
#define AS 36
#define WS 136
template <int EPI>
__device__ __forceinline__ void gemm_body(
    const float* __restrict__ A, const float* __restrict__ W,
    const float* __restrict__ bias, const float* __restrict__ res,
    float* __restrict__ C, int M, int K, int NC, int row0, int cb,
    float* A_sh, float* Whi, float* Wlo) {
    int tid = threadIdx.x;
    int lane = tid & 31, wid = tid >> 5;
    int wm = wid >> 1, wn = wid & 1;
    int g = lane >> 2, t = lane & 3;
    float acc[2][8][4];
#pragma unroll
    for (int mf = 0; mf < 2; mf++)
#pragma unroll
        for (int nf = 0; nf < 8; nf++)
#pragma unroll
            for (int u = 0; u < 4; u++) acc[mf][nf][u] = 0.f;

    int nkt = K >> 5;
    for (int kt = 0; kt < nkt; ++kt) {
#pragma unroll
        for (int it = 0; it < 4; ++it) {
            int idx = tid + it * 256;
            int r = idx >> 3, c4 = (idx & 7) << 2;
            float4 v = make_float4(0.f, 0.f, 0.f, 0.f);
            if (row0 + r < M) v = *(const float4*)(A + (size_t)(row0 + r) * K + kt * 32 + c4);
            *(float4*)(A_sh + r * AS + c4) = v;
        }
#pragma unroll
        for (int it = 0; it < 4; ++it) {
            int idx = tid + it * 256;
            int kk = idx >> 5, wc = (idx & 31) << 2;
            float4 v = *(const float4*)(W + (size_t)(kt * 32 + kk) * NC + cb + wc);
            uint32_t h, l; float4 hv, lv;
            tf32split(v.x, h, l); hv.x = __uint_as_float(h); lv.x = __uint_as_float(l);
            tf32split(v.y, h, l); hv.y = __uint_as_float(h); lv.y = __uint_as_float(l);
            tf32split(v.z, h, l); hv.z = __uint_as_float(h); lv.z = __uint_as_float(l);
            tf32split(v.w, h, l); hv.w = __uint_as_float(h); lv.w = __uint_as_float(l);
            *(float4*)(Whi + kk * WS + wc) = hv;
            *(float4*)(Wlo + kk * WS + wc) = lv;
        }
        __syncthreads();
#pragma unroll
        for (int k8 = 0; k8 < 4; ++k8) {
            int ck = k8 * 8;
            uint32_t ahi[2][4], alo[2][4];
#pragma unroll
            for (int mf = 0; mf < 2; ++mf) {
                int rb = 32 * wm + 16 * mf;
                float a0 = A_sh[(rb + g)     * AS + ck + t];
                float a1 = A_sh[(rb + g + 8) * AS + ck + t];
                float a2 = A_sh[(rb + g)     * AS + ck + t + 4];
                float a3 = A_sh[(rb + g + 8) * AS + ck + t + 4];
                tf32split(a0, ahi[mf][0], alo[mf][0]);
                tf32split(a1, ahi[mf][1], alo[mf][1]);
                tf32split(a2, ahi[mf][2], alo[mf][2]);
                tf32split(a3, ahi[mf][3], alo[mf][3]);
            }
#pragma unroll
            for (int nf = 0; nf < 8; ++nf) {
                int nb = 64 * wn + 8 * nf + g;
                uint32_t bh0 = __float_as_uint(Whi[(ck + t)     * WS + nb]);
                uint32_t bh1 = __float_as_uint(Whi[(ck + t + 4) * WS + nb]);
                uint32_t bl0 = __float_as_uint(Wlo[(ck + t)     * WS + nb]);
                uint32_t bl1 = __float_as_uint(Wlo[(ck + t + 4) * WS + nb]);
#pragma unroll
                for (int mf = 0; mf < 2; ++mf) {
                    mma8(acc[mf][nf], alo[mf], bh0, bh1);
                    mma8(acc[mf][nf], ahi[mf], bl0, bl1);
                    mma8(acc[mf][nf], ahi[mf], bh0, bh1);
                }
            }
        }
        __syncthreads();
    }
#pragma unroll
    for (int mf = 0; mf < 2; ++mf) {
#pragma unroll
        for (int nf = 0; nf < 8; ++nf) {
            int c  = cb + 64 * wn + 8 * nf + 2 * t;
            int r0 = row0 + 32 * wm + 16 * mf + g;
            float2 v0 = make_float2(acc[mf][nf][0], acc[mf][nf][1]);
            float2 v1 = make_float2(acc[mf][nf][2], acc[mf][nf][3]);
            if (EPI == 2) {
                v0.x = v0.x / (1.f + expf(-v0.x)); v0.y = v0.y / (1.f + expf(-v0.y));
                v1.x = v1.x / (1.f + expf(-v1.x)); v1.y = v1.y / (1.f + expf(-v1.y));
            }
            if (r0 < M) {
                if (EPI == 1) {
                    float2 b = *(const float2*)(bias + c);
                    float2 rr = *(const float2*)(res + (size_t)r0 * NC + c);
                    v0.x += b.x + rr.x; v0.y += b.y + rr.y;
                }
                if (EPI == 3) {
                    float2 rr = *(const float2*)(res + (size_t)r0 * NC + c);
                    v0.x += rr.x; v0.y += rr.y;
                }
                *(float2*)(C + (size_t)r0 * NC + c) = v0;
            }
            int r1 = r0 + 8;
            if (r1 < M) {
                if (EPI == 1) {
                    float2 b = *(const float2*)(bias + c);
                    float2 rr = *(const float2*)(res + (size_t)r1 * NC + c);
                    v1.x += b.x + rr.x; v1.y += b.y + rr.y;
                }
                if (EPI == 3) {
                    float2 rr = *(const float2*)(res + (size_t)r1 * NC + c);
                    v1.x += rr.x; v1.y += rr.y;
                }
                *(float2*)(C + (size_t)r1 * NC + c) = v1;
            }
        }
    }
}

#define GEMM_SMEM ((128 * AS + 2 * 32 * WS) * 4)

template <int EPI>
__global__ void __launch_bounds__(256, 2) gemm_kernel(
    const float* __restrict__ A, const float* __restrict__ W,
    const float* __restrict__ bias, const float* __restrict__ res,
    float* __restrict__ C, int M, int K, int NC) {
    extern __shared__ float gsh[];
    float* A_sh = gsh;
    float* Whi  = gsh + 128 * AS;
    float* Wlo  = Whi + 32 * WS;
    gemm_body<EPI>(A, W, bias, res, C, M, K, NC, blockIdx.x * 128, blockIdx.y * 128,
                   A_sh, Whi, Wlo);
}

__global__ void __launch_bounds__(256, 2) qkv_kernel(
    const float* __restrict__ A,
    const float* __restrict__ Wq, const float* __restrict__ Wk, const float* __restrict__ Wv,
    float* __restrict__ Q, float* __restrict__ Ko, float* __restrict__ V, int M) {
    extern __shared__ float gsh[];
    float* A_sh = gsh;
    float* Whi  = gsh + 128 * AS;
    float* Wlo  = Whi + 32 * WS;
    const float* W = (blockIdx.y == 0) ? Wq : (blockIdx.y == 1) ? Wk : Wv;
    float* C       = (blockIdx.y == 0) ? Q  : (blockIdx.y == 1) ? Ko : V;
    gemm_body<0>(A, W, nullptr, nullptr, C, M, 128, 128, blockIdx.x * 128, 0, A_sh, Whi, Wlo);
}

// ---------------- fused edge kernel: LN -> Pe GEMM (3xTF32) -> score/exp -> scatter ----
#define LN_STRIDE 132
__global__ void __launch_bounds__(256, 2) edge_kernel(
    const float* __restrict__ ef, const float* __restrict__ lnw, const float* __restrict__ lnb,
    const float* __restrict__ We, const int* __restrict__ src, const int* __restrict__ dst,
    const float* __restrict__ Q, const float* __restrict__ Kv, const float* __restrict__ V,
    float* __restrict__ wV, float* __restrict__ z, int E) {
    extern __shared__ float sh[];
    float* LN_sh = sh;
    float* Whi   = sh + 128 * LN_STRIDE;
    float* Wlo   = Whi + 32 * WS;
    int* s_sh = (int*)(Wlo + 32 * WS);
    int* d_sh = s_sh + 128;

    int tid = threadIdx.x, lane = tid & 31, w = tid >> 5;
    int e0 = blockIdx.x * 128;
    if (tid < 128) {
        int e = e0 + tid;
        s_sh[tid] = (e < E) ? src[e] : 0;
        d_sh[tid] = (e < E) ? dst[e] : 0;
    }
    float4 lw = *(const float4*)(lnw + 4 * lane);
    float4 lb = *(const float4*)(lnb + 4 * lane);
#pragma unroll
    for (int i = 0; i < 16; i++) {
        int r = w * 16 + i;
        int e = e0 + r;
        float4 v = make_float4(0.f, 0.f, 0.f, 0.f);
        if (e < E) v = *(const float4*)(ef + (size_t)e * 128 + 4 * lane);
        float s  = v.x + v.y + v.z + v.w;
        float sq = v.x * v.x + v.y * v.y + v.z * v.z + v.w * v.w;
#pragma unroll
        for (int o = 16; o; o >>= 1) {
            s  += __shfl_xor_sync(0xffffffffu, s,  o);
            sq += __shfl_xor_sync(0xffffffffu, sq, o);
        }
        float mu   = s * (1.f / 128.f);
        float rstd = rsqrtf(sq * (1.f / 128.f) - mu * mu + 1e-5f);
        float4 o4;
        o4.x = (v.x - mu) * rstd * lw.x + lb.x;
        o4.y = (v.y - mu) * rstd * lw.y + lb.y;
        o4.z = (v.z - mu) * rstd * lw.z + lb.z;
        o4.w = (v.w - mu) * rstd * lw.w + lb.w;
        *(float4*)(LN_sh + r * LN_STRIDE + 4 * lane) = o4;
    }
    __syncthreads();
    int wm = w >> 1, wn = w & 1;
    int g = lane >> 2, t = lane & 3;
    float acc[2][8][4];
#pragma unroll
    for (int mf = 0; mf < 2; mf++)
#pragma unroll
        for (int nf = 0; nf < 8; nf++)
#pragma unroll
            for (int u = 0; u < 4; u++) acc[mf][nf][u] = 0.f;
    for (int kt = 0; kt < 4; ++kt) {
#pragma unroll
        for (int it = 0; it < 4; ++it) {
            int idx = tid + it * 256;
            int kk = idx >> 5, wc = (idx & 31) << 2;
            float4 v = *(const float4*)(We + (size_t)(kt * 32 + kk) * 128 + wc);
            uint32_t h, l; float4 hv, lv;
            tf32split(v.x, h, l); hv.x = __uint_as_float(h); lv.x = __uint_as_float(l);
            tf32split(v.y, h, l); hv.y = __uint_as_float(h); lv.y = __uint_as_float(l);
            tf32split(v.z, h, l); hv.z = __uint_as_float(h); lv.z = __uint_as_float(l);
            tf32split(v.w, h, l); hv.w = __uint_as_float(h); lv.w = __uint_as_float(l);
            *(float4*)(Whi + kk * WS + wc) = hv;
            *(float4*)(Wlo + kk * WS + wc) = lv;
        }
        __syncthreads();
#pragma unroll
        for (int k8 = 0; k8 < 4; ++k8) {
            int ckA = kt * 32 + k8 * 8;
            int ckW = k8 * 8;
            uint32_t ahi[2][4], alo[2][4];
#pragma unroll
            for (int mf = 0; mf < 2; ++mf) {
                int rb = 32 * wm + 16 * mf;
                float a0 = LN_sh[(rb + g)     * LN_STRIDE + ckA + t];
                float a1 = LN_sh[(rb + g + 8) * LN_STRIDE + ckA + t];
                float a2 = LN_sh[(rb + g)     * LN_STRIDE + ckA + t + 4];
                float a3 = LN_sh[(rb + g + 8) * LN_STRIDE + ckA + t + 4];
                tf32split(a0, ahi[mf][0], alo[mf][0]);
                tf32split(a1, ahi[mf][1], alo[mf][1]);
                tf32split(a2, ahi[mf][2], alo[mf][2]);
                tf32split(a3, ahi[mf][3], alo[mf][3]);
            }
#pragma unroll
            for (int nf = 0; nf < 8; ++nf) {
                int nb = 64 * wn + 8 * nf + g;
                uint32_t bh0 = __float_as_uint(Whi[(ckW + t)     * WS + nb]);
                uint32_t bh1 = __float_as_uint(Whi[(ckW + t + 4) * WS + nb]);
                uint32_t bl0 = __float_as_uint(Wlo[(ckW + t)     * WS + nb]);
                uint32_t bl1 = __float_as_uint(Wlo[(ckW + t + 4) * WS + nb]);
#pragma unroll
                for (int mf = 0; mf < 2; ++mf) {
                    mma8(acc[mf][nf], alo[mf], bh0, bh1);
                    mma8(acc[mf][nf], ahi[mf], bl0, bl1);
                    mma8(acc[mf][nf], ahi[mf], bh0, bh1);
                }
            }
        }
        __syncthreads();
    }
#pragma unroll
    for (int mf = 0; mf < 2; ++mf) {
#pragma unroll
        for (int nf = 0; nf < 8; ++nf) {
            int r0 = 32 * wm + 16 * mf + g;
            int c  = 64 * wn + 8 * nf + 2 * t;
            *(float2*)(LN_sh + r0 * LN_STRIDE + c)       = make_float2(acc[mf][nf][0], acc[mf][nf][1]);
            *(float2*)(LN_sh + (r0 + 8) * LN_STRIDE + c) = make_float2(acc[mf][nf][2], acc[mf][nf][3]);
        }
    }
    __syncthreads();
    const float inv = 0.17677669529663687f;
    int head = lane >> 3;
    int base = w * 16;
    int si = s_sh[base], di = d_sh[base];
    float4 kq = *(const float4*)(Kv + (size_t)si * 128 + 4 * lane);
    float4 qv = *(const float4*)(Q  + (size_t)di * 128 + 4 * lane);
    float4 vv = *(const float4*)(V  + (size_t)si * 128 + 4 * lane);
#pragma unroll
    for (int j = 0; j < 16; j++) {
        int e = e0 + base + j;
        float4 kqc = kq, qvc = qv, vvc = vv;
        int dic = di;
        if (j < 15) {
            int sn = s_sh[base + j + 1], dn = d_sh[base + j + 1];
            kq = *(const float4*)(Kv + (size_t)sn * 128 + 4 * lane);
            qv = *(const float4*)(Q  + (size_t)dn * 128 + 4 * lane);
            vv = *(const float4*)(V  + (size_t)sn * 128 + 4 * lane);
            di = dn;
        }
        if (e < E) {
            float4 pe = *(float4*)(LN_sh + (base + j) * LN_STRIDE + 4 * lane);
            float tt = clip5(kqc.x * qvc.x * inv) * pe.x + clip5(kqc.y * qvc.y * inv) * pe.y
                     + clip5(kqc.z * qvc.z * inv) * pe.z + clip5(kqc.w * qvc.w * inv) * pe.w;
            tt += __shfl_xor_sync(0xffffffffu, tt, 1);
            tt += __shfl_xor_sync(0xffffffffu, tt, 2);
            tt += __shfl_xor_sync(0xffffffffu, tt, 4);
            float s = expf(clip5(tt));
            float* dp = wV + (size_t)dic * 128 + 4 * lane;
            red_add_v4(dp, vvc.x * s, vvc.y * s, vvc.z * s, vvc.w * s);
            if ((lane & 7) == 0) red_add_f(z + (size_t)dic * 4 + head, s);
        }
    }
}
#define EDGE_SMEM ((128 * LN_STRIDE + 2 * 32 * WS) * 4 + 2 * 128 * 4)

// ---------------- attn = wV / (z + 1e-6) ----------------
__global__ void attn_kernel(const float* __restrict__ wV, const float* __restrict__ z,
                            float* __restrict__ outp, int N) {
    int i = blockIdx.x * blockDim.x + threadIdx.x;
    if (i >= N * 32) return;
    int n = i >> 5;
    int head = (i & 31) >> 3;
    float invz = 1.f / (z[(size_t)n * 4 + head] + 1e-6f);
    float4 v = *(const float4*)(wV + (size_t)i * 4);
    v.x *= invz; v.y *= invz; v.z *= invz; v.w *= invz;
    *(float4*)(outp + (size_t)i * 4) = v;
}

// ---------------- Set2Set: one block per graph, all 3 iterations internal ----------------
__global__ void __launch_bounds__(256) set2set_kernel(
    const float* __restrict__ nf, const int* __restrict__ gid,
    const float* __restrict__ W_ih, const float* __restrict__ W_hh,
    const float* __restrict__ b_ih, const float* __restrict__ b_hh,
    float* __restrict__ ener, float* __restrict__ out, int N) {
    __shared__ float qs[256], hh[128], cc[128], gates[512], rsh[8 * 128], red[16];
    int tid = threadIdx.x, lane = tid & 31, w = tid >> 5;
    int g = blockIdx.x;
    int lo, hi;
    {
        int a = 0, b = N;
        while (a < b) { int m = (a + b) >> 1; if (gid[m] < g) a = m + 1; else b = m; }
        lo = a;
        b = N;
        while (a < b) { int m = (a + b) >> 1; if (gid[m] < g + 1) a = m + 1; else b = m; }
        hi = a;
    }
    qs[tid] = 0.f;
    if (tid < 128) { hh[tid] = 0.f; cc[tid] = 0.f; }
    __syncthreads();

    for (int it = 0; it < 3; ++it) {
        for (int j = tid; j < 512; j += 256) {
            float acc = b_ih[j] + b_hh[j];
            const float* wi = W_ih + (size_t)j * 256;
#pragma unroll 8
            for (int k2 = 0; k2 < 256; k2++) acc += qs[k2] * wi[k2];
            const float* whp = W_hh + (size_t)j * 128;
#pragma unroll 8
            for (int k2 = 0; k2 < 128; k2++) acc += hh[k2] * whp[k2];
            gates[j] = acc;
        }
        __syncthreads();
        if (tid < 128) {
            float c = sigm(gates[128 + tid]) * cc[tid] + sigm(gates[tid]) * tanhf(gates[256 + tid]);
            cc[tid] = c;
            hh[tid] = sigm(gates[384 + tid]) * tanhf(c);
        }
        __syncthreads();
        float mloc = -INFINITY;
        float4 h4 = *(float4*)&hh[4 * lane];
        for (int n = lo + w; n < hi; n += 8) {
            float4 a4 = *(const float4*)(nf + (size_t)n * 128 + 4 * lane);
            float t = a4.x * h4.x + a4.y * h4.y + a4.z * h4.z + a4.w * h4.w;
#pragma unroll
            for (int o = 16; o; o >>= 1) t += __shfl_xor_sync(0xffffffffu, t, o);
            if (lane == 0) ener[n] = t;
            mloc = fmaxf(mloc, t);
        }
#pragma unroll
        for (int o = 16; o; o >>= 1) mloc = fmaxf(mloc, __shfl_xor_sync(0xffffffffu, mloc, o));
        if (lane == 0) red[w] = mloc;
        __syncthreads();
        if (tid == 0) {
            float m = -INFINITY;
            for (int i = 0; i < 8; i++) m = fmaxf(m, red[i]);
            red[8] = m;
        }
        __syncthreads();
        float m = red[8];
        float dloc = 0.f;
        for (int n = lo + tid; n < hi; n += 256) dloc += expf(ener[n] - m);
#pragma unroll
        for (int o = 16; o; o >>= 1) dloc += __shfl_xor_sync(0xffffffffu, dloc, o);
        __syncthreads();
        if (lane == 0) red[w] = dloc;
        __syncthreads();
        if (tid == 0) {
            float d = 0.f;
            for (int i = 0; i < 8; i++) d += red[i];
            red[9] = d;
        }
        __syncthreads();
        float invd = 1.f / red[9];
        float4 racc = make_float4(0.f, 0.f, 0.f, 0.f);
        for (int n = lo + w; n < hi; n += 8) {
            float coef = expf(ener[n] - m) * invd;
            float4 a4 = *(const float4*)(nf + (size_t)n * 128 + 4 * lane);
            racc.x += coef * a4.x; racc.y += coef * a4.y;
            racc.z += coef * a4.z; racc.w += coef * a4.w;
        }
        *(float4*)&rsh[w * 128 + 4 * lane] = racc;
        __syncthreads();
        if (tid < 128) {
            float ro = 0.f;
#pragma unroll
            for (int i = 0; i < 8; i++) ro += rsh[i * 128 + tid];
            qs[tid] = hh[tid];
            qs[128 + tid] = ro;
        }
        __syncthreads();
    }
    out[(size_t)g * 256 + tid] = qs[tid];
}

// ---------------- launch ----------------
extern "C" void kernel_launch(void* const* d_in, const int* in_sizes, int n_in,
                              void* d_out, int out_size) {
    const float* node = (const float*)d_in[0];
    const float* edge = (const float*)d_in[1];
    const float* Wq = (const float*)d_in[2];
    const float* Wk = (const float*)d_in[3];
    const float* Wv = (const float*)d_in[4];
    const float* We = (const float*)d_in[5];
    const float* Wo = (const float*)d_in[6];
    const float* bo = (const float*)d_in[7];
    const float* W1 = (const float*)d_in[8];
    const float* W2 = (const float*)d_in[9];
    const float* l1nw = (const float*)d_in[10];
    const float* l1nb = (const float*)d_in[11];
    const float* l1ew = (const float*)d_in[12];
    const float* l1eb = (const float*)d_in[13];
    const float* l2w = (const float*)d_in[14];
    const float* l2b = (const float*)d_in[15];
    const float* Wih = (const float*)d_in[16];
    const float* Whh = (const float*)d_in[17];
    const float* bih = (const float*)d_in[18];
    const float* bhh = (const float*)d_in[19];
    const int* src = (const int*)d_in[20];
    const int* dst = (const int*)d_in[21];
    const int* gid = (const int*)d_in[22];

    int N = in_sizes[0] / 128;
    int E = in_sizes[20];
    int G = out_size / 256;

    float *b1, *q, *k, *v, *x, *wv, *z, *t, *en;
    cudaGetSymbolAddress((void**)&b1, g_b1);
    cudaGetSymbolAddress((void**)&q,  g_Q);
    cudaGetSymbolAddress((void**)&k,  g_K);
    cudaGetSymbolAddress((void**)&v,  g_V);
    cudaGetSymbolAddress((void**)&x,  g_x);
    cudaGetSymbolAddress((void**)&wv, g_wV);
    cudaGetSymbolAddress((void**)&z,  g_z);
    cudaGetSymbolAddress((void**)&t,  g_t);
    cudaGetSymbolAddress((void**)&en, g_en);

    cudaFuncSetAttribute(edge_kernel, cudaFuncAttributeMaxDynamicSharedMemorySize, EDGE_SMEM);
    cudaFuncSetAttribute(qkv_kernel, cudaFuncAttributeMaxDynamicSharedMemorySize, GEMM_SMEM);
    cudaFuncSetAttribute(gemm_kernel<1>, cudaFuncAttributeMaxDynamicSharedMemorySize, GEMM_SMEM);
    cudaFuncSetAttribute(gemm_kernel<2>, cudaFuncAttributeMaxDynamicSharedMemorySize, GEMM_SMEM);
    cudaFuncSetAttribute(gemm_kernel<3>, cudaFuncAttributeMaxDynamicSharedMemorySize, GEMM_SMEM);

    int gnodes = (N + 127) / 128;

    ln_kernel<<<(N + 7) / 8, 256>>>(node, b1, l1nw, l1nb, N);
    qkv_kernel<<<dim3(gnodes, 3), 256, GEMM_SMEM>>>(b1, Wq, Wk, Wv, q, k, v, N);
    fzero2_kernel<<<(N * 33 + 255) / 256, 256>>>((float4*)wv, (float4*)z, N * 32, N);
    edge_kernel<<<(E + 127) / 128, 256, EDGE_SMEM>>>(edge, l1ew, l1eb, We, src, dst,
                                                     q, k, v, wv, z, E);
    attn_kernel<<<(N * 32 + 255) / 256, 256>>>(wv, z, b1, N);
    gemm_kernel<1><<<dim3(gnodes, 1), 256, GEMM_SMEM>>>(b1, Wo, bo, node, x, N, 128, 128);
    ln_kernel<<<(N + 7) / 8, 256>>>(x, q, l2w, l2b, N);
    gemm_kernel<2><<<dim3(gnodes, 2), 256, GEMM_SMEM>>>(q, W1, nullptr, nullptr, t, N, 128, 256);
    gemm_kernel<3><<<dim3(gnodes, 1), 256, GEMM_SMEM>>>(t, W2, nullptr, x, k, N, 256, 128);
    set2set_kernel<<<G, 256>>>(k, gid, Wih, Whh, bih, bhh, en, (float*)d_out, N);
}

// round 13
// speedup vs baseline: 1.5571x; 1.1097x over previous
#include <cuda_runtime.h>
#include <math.h>
#include <stdint.h>

#define MAXN 50048
#define MAXE 600064

// ---------------- scratch (static device globals; no allocation) ----------------
__device__ float g_b1[(size_t)MAXN * 128];
__device__ float g_Q [(size_t)MAXN * 128];
__device__ float g_K [(size_t)MAXN * 128];
__device__ float g_V [(size_t)MAXN * 128];
__device__ float g_x [(size_t)MAXN * 128];
__device__ float g_wV[(size_t)MAXN * 128];
__device__ float g_z [(size_t)MAXN * 4];
__device__ float g_t [(size_t)MAXN * 256];
__device__ float g_en[(size_t)MAXN];

__device__ __forceinline__ float clip5(float x) { return fminf(fmaxf(x, -5.f), 5.f); }
__device__ __forceinline__ float sigm(float x)  { return 1.f / (1.f + expf(-x)); }

__device__ __forceinline__ void red_add_v4(float* p, float a, float b, float c, float d) {
    asm volatile("red.global.add.v4.f32 [%0], {%1,%2,%3,%4};"
                 :: "l"(p), "f"(a), "f"(b), "f"(c), "f"(d) : "memory");
}
__device__ __forceinline__ void red_add_f(float* p, float v) {
    asm volatile("red.global.add.f32 [%0], %1;" :: "l"(p), "f"(v) : "memory");
}

// ---- TF32 helpers ----
__device__ __forceinline__ void tf32split(float x, uint32_t& hi, uint32_t& lo) {
    uint32_t h; asm("cvt.rna.tf32.f32 %0, %1;" : "=r"(h) : "f"(x));
    float hf = __uint_as_float(h);
    float l = x - hf;
    uint32_t lr; asm("cvt.rna.tf32.f32 %0, %1;" : "=r"(lr) : "f"(l));
    hi = h; lo = lr;
}
__device__ __forceinline__ float tf32r(float x) {
    uint32_t h; asm("cvt.rna.tf32.f32 %0, %1;" : "=r"(h) : "f"(x));
    return __uint_as_float(h);
}
__device__ __forceinline__ void mma8(float* d, const uint32_t* a, uint32_t b0, uint32_t b1) {
    asm volatile("mma.sync.aligned.m16n8k8.row.col.f32.tf32.tf32.f32 "
        "{%0,%1,%2,%3}, {%4,%5,%6,%7}, {%8,%9}, {%0,%1,%2,%3};"
        : "+f"(d[0]), "+f"(d[1]), "+f"(d[2]), "+f"(d[3])
        : "r"(a[0]), "r"(a[1]), "r"(a[2]), "r"(a[3]), "r"(b0), "r"(b1));
}

// ---------------- zero fill (wV and z in ONE launch) ----------------
__global__ void fzero2_kernel(float4* __restrict__ wv, float4* __restrict__ z,
                              int nwv4, int nz4) {
    int i = blockIdx.x * blockDim.x + threadIdx.x;
    if (i < nwv4) wv[i] = make_float4(0.f, 0.f, 0.f, 0.f);
    else {
        int j = i - nwv4;
        if (j < nz4) z[j] = make_float4(0.f, 0.f, 0.f, 0.f);
    }
}

// ---------------- row LayerNorm (warp per 128-wide row) ----------------
__global__ void ln_kernel(const float* __restrict__ in, float* __restrict__ out,
                          const float* __restrict__ w, const float* __restrict__ b, int rows) {
    int warp = (blockIdx.x * blockDim.x + threadIdx.x) >> 5;
    int lane = threadIdx.x & 31;
    if (warp >= rows) return;
    float4 v = *(const float4*)(in + (size_t)warp * 128 + 4 * lane);
    float s  = v.x + v.y + v.z + v.w;
    float sq = v.x * v.x + v.y * v.y + v.z * v.z + v.w * v.w;
#pragma unroll
    for (int o = 16; o; o >>= 1) {
        s  += __shfl_xor_sync(0xffffffffu, s,  o);
        sq += __shfl_xor_sync(0xffffffffu, sq, o);
    }
    float mu   = s * (1.f / 128.f);
    float rstd = rsqrtf(sq * (1.f / 128.f) - mu * mu + 1e-5f);
    float4 wv = *(const float4*)(w + 4 * lane);
    float4 bv = *(const float4*)(b + 4 * lane);
    float4 o4;
    o4.x = (v.x - mu) * rstd * wv.x + bv.x;
    o4.y = (v.y - mu) * rstd * wv.y + bv.y;
    o4.z = (v.z - mu) * rstd * wv.z + bv.z;
    o4.w = (v.w - mu) * rstd * wv.w + bv.w;
    *(float4*)(out + (size_t)warp * 128 + 4 * lane) = o4;
}

// ---------------- tensor GEMM body: 128x128, A-side 2xTF32 (A pre-rounded at staging) --
// 8 warps = 4(m) x 2(n); warp tile 32x64.
// A_sh [128][36] tf32-rounded fp32; Whi/Wlo [32][136].
#define AS 36
#define WS 136
template <int EPI>
__device__ __forceinline__ void gemm_body(
    const float* __restrict__ A, const float* __restrict__ W,
    const float* __restrict__ bias, const float* __restrict__ res,
    float* __restrict__ C, int M, int K, int NC, int row0, int cb,
    float* A_sh, float* Whi, float* Wlo) {
    int tid = threadIdx.x;
    int lane = tid & 31, wid = tid >> 5;
    int wm = wid >> 1, wn = wid & 1;
    int g = lane >> 2, t = lane & 3;
    float acc[2][8][4];
#pragma unroll
    for (int mf = 0; mf < 2; mf++)
#pragma unroll
        for (int nf = 0; nf < 8; nf++)
#pragma unroll
            for (int u = 0; u < 4; u++) acc[mf][nf][u] = 0.f;

    int nkt = K >> 5;
    for (int kt = 0; kt < nkt; ++kt) {
#pragma unroll
        for (int it = 0; it < 4; ++it) {   // A chunk 128x32, rounded to tf32 at staging
            int idx = tid + it * 256;
            int r = idx >> 3, c4 = (idx & 7) << 2;
            float4 v = make_float4(0.f, 0.f, 0.f, 0.f);
            if (row0 + r < M) v = *(const float4*)(A + (size_t)(row0 + r) * K + kt * 32 + c4);
            v.x = tf32r(v.x); v.y = tf32r(v.y); v.z = tf32r(v.z); v.w = tf32r(v.w);
            *(float4*)(A_sh + r * AS + c4) = v;
        }
#pragma unroll
        for (int it = 0; it < 4; ++it) {   // W chunk 32x128 -> hi/lo
            int idx = tid + it * 256;
            int kk = idx >> 5, wc = (idx & 31) << 2;
            float4 v = *(const float4*)(W + (size_t)(kt * 32 + kk) * NC + cb + wc);
            uint32_t h, l; float4 hv, lv;
            tf32split(v.x, h, l); hv.x = __uint_as_float(h); lv.x = __uint_as_float(l);
            tf32split(v.y, h, l); hv.y = __uint_as_float(h); lv.y = __uint_as_float(l);
            tf32split(v.z, h, l); hv.z = __uint_as_float(h); lv.z = __uint_as_float(l);
            tf32split(v.w, h, l); hv.w = __uint_as_float(h); lv.w = __uint_as_float(l);
            *(float4*)(Whi + kk * WS + wc) = hv;
            *(float4*)(Wlo + kk * WS + wc) = lv;
        }
        __syncthreads();
#pragma unroll
        for (int k8 = 0; k8 < 4; ++k8) {
            int ck = k8 * 8;
            uint32_t a[2][4];
#pragma unroll
            for (int mf = 0; mf < 2; ++mf) {
                int rb = 32 * wm + 16 * mf;
                a[mf][0] = __float_as_uint(A_sh[(rb + g)     * AS + ck + t]);
                a[mf][1] = __float_as_uint(A_sh[(rb + g + 8) * AS + ck + t]);
                a[mf][2] = __float_as_uint(A_sh[(rb + g)     * AS + ck + t + 4]);
                a[mf][3] = __float_as_uint(A_sh[(rb + g + 8) * AS + ck + t + 4]);
            }
#pragma unroll
            for (int nf = 0; nf < 8; ++nf) {
                int nb = 64 * wn + 8 * nf + g;
                uint32_t bh0 = __float_as_uint(Whi[(ck + t)     * WS + nb]);
                uint32_t bh1 = __float_as_uint(Whi[(ck + t + 4) * WS + nb]);
                uint32_t bl0 = __float_as_uint(Wlo[(ck + t)     * WS + nb]);
                uint32_t bl1 = __float_as_uint(Wlo[(ck + t + 4) * WS + nb]);
#pragma unroll
                for (int mf = 0; mf < 2; ++mf) {
                    mma8(acc[mf][nf], a[mf], bl0, bl1);
                    mma8(acc[mf][nf], a[mf], bh0, bh1);
                }
            }
        }
        __syncthreads();
    }
#pragma unroll
    for (int mf = 0; mf < 2; ++mf) {
#pragma unroll
        for (int nf = 0; nf < 8; ++nf) {
            int c  = cb + 64 * wn + 8 * nf + 2 * t;
            int r0 = row0 + 32 * wm + 16 * mf + g;
            float2 v0 = make_float2(acc[mf][nf][0], acc[mf][nf][1]);
            float2 v1 = make_float2(acc[mf][nf][2], acc[mf][nf][3]);
            if (EPI == 2) {
                v0.x = v0.x / (1.f + expf(-v0.x)); v0.y = v0.y / (1.f + expf(-v0.y));
                v1.x = v1.x / (1.f + expf(-v1.x)); v1.y = v1.y / (1.f + expf(-v1.y));
            }
            if (r0 < M) {
                if (EPI == 1) {
                    float2 b = *(const float2*)(bias + c);
                    float2 rr = *(const float2*)(res + (size_t)r0 * NC + c);
                    v0.x += b.x + rr.x; v0.y += b.y + rr.y;
                }
                if (EPI == 3) {
                    float2 rr = *(const float2*)(res + (size_t)r0 * NC + c);
                    v0.x += rr.x; v0.y += rr.y;
                }
                *(float2*)(C + (size_t)r0 * NC + c) = v0;
            }
            int r1 = r0 + 8;
            if (r1 < M) {
                if (EPI == 1) {
                    float2 b = *(const float2*)(bias + c);
                    float2 rr = *(const float2*)(res + (size_t)r1 * NC + c);
                    v1.x += b.x + rr.x; v1.y += b.y + rr.y;
                }
                if (EPI == 3) {
                    float2 rr = *(const float2*)(res + (size_t)r1 * NC + c);
                    v1.x += rr.x; v1.y += rr.y;
                }
                *(float2*)(C + (size_t)r1 * NC + c) = v1;
            }
        }
    }
}

#define GEMM_SMEM ((128 * AS + 2 * 32 * WS) * 4)

template <int EPI>
__global__ void __launch_bounds__(256, 2) gemm_kernel(
    const float* __restrict__ A, const float* __restrict__ W,
    const float* __restrict__ bias, const float* __restrict__ res,
    float* __restrict__ C, int M, int K, int NC) {
    extern __shared__ float gsh[];
    float* A_sh = gsh;
    float* Whi  = gsh + 128 * AS;
    float* Wlo  = Whi + 32 * WS;
    gemm_body<EPI>(A, W, bias, res, C, M, K, NC, blockIdx.x * 128, blockIdx.y * 128,
                   A_sh, Whi, Wlo);
}

__global__ void __launch_bounds__(256, 2) qkv_kernel(
    const float* __restrict__ A,
    const float* __restrict__ Wq, const float* __restrict__ Wk, const float* __restrict__ Wv,
    float* __restrict__ Q, float* __restrict__ Ko, float* __restrict__ V, int M) {
    extern __shared__ float gsh[];
    float* A_sh = gsh;
    float* Whi  = gsh + 128 * AS;
    float* Wlo  = Whi + 32 * WS;
    const float* W = (blockIdx.y == 0) ? Wq : (blockIdx.y == 1) ? Wk : Wv;
    float* C       = (blockIdx.y == 0) ? Q  : (blockIdx.y == 1) ? Ko : V;
    gemm_body<0>(A, W, nullptr, nullptr, C, M, 128, 128, blockIdx.x * 128, 0, A_sh, Whi, Wlo);
}

// ---------------- fused edge kernel: LN -> Pe GEMM (A-side 2xTF32) -> score -> scatter --
#define LN_STRIDE 132
__global__ void __launch_bounds__(256, 2) edge_kernel(
    const float* __restrict__ ef, const float* __restrict__ lnw, const float* __restrict__ lnb,
    const float* __restrict__ We, const int* __restrict__ src, const int* __restrict__ dst,
    const float* __restrict__ Q, const float* __restrict__ Kv, const float* __restrict__ V,
    float* __restrict__ wV, float* __restrict__ z, int E) {
    extern __shared__ float sh[];
    float* LN_sh = sh;                           // [128][132] tf32-rounded LN, later Pe
    float* Whi   = sh + 128 * LN_STRIDE;         // [32][136]
    float* Wlo   = Whi + 32 * WS;                // [32][136]
    int* s_sh = (int*)(Wlo + 32 * WS);           // [128]
    int* d_sh = s_sh + 128;                      // [128]

    int tid = threadIdx.x, lane = tid & 31, w = tid >> 5;
    int e0 = blockIdx.x * 128;
    if (tid < 128) {
        int e = e0 + tid;
        s_sh[tid] = (e < E) ? src[e] : 0;
        d_sh[tid] = (e < E) ? dst[e] : 0;
    }
    float4 lw = *(const float4*)(lnw + 4 * lane);
    float4 lb = *(const float4*)(lnb + 4 * lane);
    // phase A: LN, stored tf32-rounded
#pragma unroll
    for (int i = 0; i < 16; i++) {
        int r = w * 16 + i;
        int e = e0 + r;
        float4 v = make_float4(0.f, 0.f, 0.f, 0.f);
        if (e < E) v = *(const float4*)(ef + (size_t)e * 128 + 4 * lane);
        float s  = v.x + v.y + v.z + v.w;
        float sq = v.x * v.x + v.y * v.y + v.z * v.z + v.w * v.w;
#pragma unroll
        for (int o = 16; o; o >>= 1) {
            s  += __shfl_xor_sync(0xffffffffu, s,  o);
            sq += __shfl_xor_sync(0xffffffffu, sq, o);
        }
        float mu   = s * (1.f / 128.f);
        float rstd = rsqrtf(sq * (1.f / 128.f) - mu * mu + 1e-5f);
        float4 o4;
        o4.x = tf32r((v.x - mu) * rstd * lw.x + lb.x);
        o4.y = tf32r((v.y - mu) * rstd * lw.y + lb.y);
        o4.z = tf32r((v.z - mu) * rstd * lw.z + lb.z);
        o4.w = tf32r((v.w - mu) * rstd * lw.w + lb.w);
        *(float4*)(LN_sh + r * LN_STRIDE + 4 * lane) = o4;
    }
    __syncthreads();
    // phase B: Pe = LN @ We (A single tf32 plane, B hi+lo)
    int wm = w >> 1, wn = w & 1;
    int g = lane >> 2, t = lane & 3;
    float acc[2][8][4];
#pragma unroll
    for (int mf = 0; mf < 2; mf++)
#pragma unroll
        for (int nf = 0; nf < 8; nf++)
#pragma unroll
            for (int u = 0; u < 4; u++) acc[mf][nf][u] = 0.f;
    for (int kt = 0; kt < 4; ++kt) {
#pragma unroll
        for (int it = 0; it < 4; ++it) {
            int idx = tid + it * 256;
            int kk = idx >> 5, wc = (idx & 31) << 2;
            float4 v = *(const float4*)(We + (size_t)(kt * 32 + kk) * 128 + wc);
            uint32_t h, l; float4 hv, lv;
            tf32split(v.x, h, l); hv.x = __uint_as_float(h); lv.x = __uint_as_float(l);
            tf32split(v.y, h, l); hv.y = __uint_as_float(h); lv.y = __uint_as_float(l);
            tf32split(v.z, h, l); hv.z = __uint_as_float(h); lv.z = __uint_as_float(l);
            tf32split(v.w, h, l); hv.w = __uint_as_float(h); lv.w = __uint_as_float(l);
            *(float4*)(Whi + kk * WS + wc) = hv;
            *(float4*)(Wlo + kk * WS + wc) = lv;
        }
        __syncthreads();
#pragma unroll
        for (int k8 = 0; k8 < 4; ++k8) {
            int ckA = kt * 32 + k8 * 8;
            int ckW = k8 * 8;
            uint32_t a[2][4];
#pragma unroll
            for (int mf = 0; mf < 2; ++mf) {
                int rb = 32 * wm + 16 * mf;
                a[mf][0] = __float_as_uint(LN_sh[(rb + g)     * LN_STRIDE + ckA + t]);
                a[mf][1] = __float_as_uint(LN_sh[(rb + g + 8) * LN_STRIDE + ckA + t]);
                a[mf][2] = __float_as_uint(LN_sh[(rb + g)     * LN_STRIDE + ckA + t + 4]);
                a[mf][3] = __float_as_uint(LN_sh[(rb + g + 8) * LN_STRIDE + ckA + t + 4]);
            }
#pragma unroll
            for (int nf = 0; nf < 8; ++nf) {
                int nb = 64 * wn + 8 * nf + g;
                uint32_t bh0 = __float_as_uint(Whi[(ckW + t)     * WS + nb]);
                uint32_t bh1 = __float_as_uint(Whi[(ckW + t + 4) * WS + nb]);
                uint32_t bl0 = __float_as_uint(Wlo[(ckW + t)     * WS + nb]);
                uint32_t bl1 = __float_as_uint(Wlo[(ckW + t + 4) * WS + nb]);
#pragma unroll
                for (int mf = 0; mf < 2; ++mf) {
                    mma8(acc[mf][nf], a[mf], bl0, bl1);
                    mma8(acc[mf][nf], a[mf], bh0, bh1);
                }
            }
        }
        __syncthreads();
    }
    // stash Pe into LN_sh
#pragma unroll
    for (int mf = 0; mf < 2; ++mf) {
#pragma unroll
        for (int nf = 0; nf < 8; ++nf) {
            int r0 = 32 * wm + 16 * mf + g;
            int c  = 64 * wn + 8 * nf + 2 * t;
            *(float2*)(LN_sh + r0 * LN_STRIDE + c)       = make_float2(acc[mf][nf][0], acc[mf][nf][1]);
            *(float2*)(LN_sh + (r0 + 8) * LN_STRIDE + c) = make_float2(acc[mf][nf][2], acc[mf][nf][3]);
        }
    }
    __syncthreads();
    // phase C: per-edge score, exp, scatter (16 edges per warp, prefetched)
    const float inv = 0.17677669529663687f;
    int head = lane >> 3;
    int base = w * 16;
    int si = s_sh[base], di = d_sh[base];
    float4 kq = *(const float4*)(Kv + (size_t)si * 128 + 4 * lane);
    float4 qv = *(const float4*)(Q  + (size_t)di * 128 + 4 * lane);
    float4 vv = *(const float4*)(V  + (size_t)si * 128 + 4 * lane);
#pragma unroll
    for (int j = 0; j < 16; j++) {
        int e = e0 + base + j;
        float4 kqc = kq, qvc = qv, vvc = vv;
        int dic = di;
        if (j < 15) {
            int sn = s_sh[base + j + 1], dn = d_sh[base + j + 1];
            kq = *(const float4*)(Kv + (size_t)sn * 128 + 4 * lane);
            qv = *(const float4*)(Q  + (size_t)dn * 128 + 4 * lane);
            vv = *(const float4*)(V  + (size_t)sn * 128 + 4 * lane);
            di = dn;
        }
        if (e < E) {
            float4 pe = *(float4*)(LN_sh + (base + j) * LN_STRIDE + 4 * lane);
            float tt = clip5(kqc.x * qvc.x * inv) * pe.x + clip5(kqc.y * qvc.y * inv) * pe.y
                     + clip5(kqc.z * qvc.z * inv) * pe.z + clip5(kqc.w * qvc.w * inv) * pe.w;
            tt += __shfl_xor_sync(0xffffffffu, tt, 1);
            tt += __shfl_xor_sync(0xffffffffu, tt, 2);
            tt += __shfl_xor_sync(0xffffffffu, tt, 4);
            float s = expf(clip5(tt));
            float* dp = wV + (size_t)dic * 128 + 4 * lane;
            red_add_v4(dp, vvc.x * s, vvc.y * s, vvc.z * s, vvc.w * s);
            if ((lane & 7) == 0) red_add_f(z + (size_t)dic * 4 + head, s);
        }
    }
}
#define EDGE_SMEM ((128 * LN_STRIDE + 2 * 32 * WS) * 4 + 2 * 128 * 4)

// ---------------- attn = wV / (z + 1e-6) ----------------
__global__ void attn_kernel(const float* __restrict__ wV, const float* __restrict__ z,
                            float* __restrict__ outp, int N) {
    int i = blockIdx.x * blockDim.x + threadIdx.x;
    if (i >= N * 32) return;
    int n = i >> 5;
    int head = (i & 31) >> 3;
    float invz = 1.f / (z[(size_t)n * 4 + head] + 1e-6f);
    float4 v = *(const float4*)(wV + (size_t)i * 4);
    v.x *= invz; v.y *= invz; v.z *= invz; v.w *= invz;
    *(float4*)(outp + (size_t)i * 4) = v;
}

// ---------------- Set2Set: one block per graph, all 3 iterations internal ----------------
__global__ void __launch_bounds__(256) set2set_kernel(
    const float* __restrict__ nf, const int* __restrict__ gid,
    const float* __restrict__ W_ih, const float* __restrict__ W_hh,
    const float* __restrict__ b_ih, const float* __restrict__ b_hh,
    float* __restrict__ ener, float* __restrict__ out, int N) {
    __shared__ float qs[256], hh[128], cc[128], gates[512], rsh[8 * 128], red[16];
    int tid = threadIdx.x, lane = tid & 31, w = tid >> 5;
    int g = blockIdx.x;
    int lo, hi;
    {
        int a = 0, b = N;
        while (a < b) { int m = (a + b) >> 1; if (gid[m] < g) a = m + 1; else b = m; }
        lo = a;
        b = N;
        while (a < b) { int m = (a + b) >> 1; if (gid[m] < g + 1) a = m + 1; else b = m; }
        hi = a;
    }
    qs[tid] = 0.f;
    if (tid < 128) { hh[tid] = 0.f; cc[tid] = 0.f; }
    __syncthreads();

    for (int it = 0; it < 3; ++it) {
        for (int j = tid; j < 512; j += 256) {
            float acc = b_ih[j] + b_hh[j];
            const float* wi = W_ih + (size_t)j * 256;
#pragma unroll 8
            for (int k2 = 0; k2 < 256; k2++) acc += qs[k2] * wi[k2];
            const float* whp = W_hh + (size_t)j * 128;
#pragma unroll 8
            for (int k2 = 0; k2 < 128; k2++) acc += hh[k2] * whp[k2];
            gates[j] = acc;
        }
        __syncthreads();
        if (tid < 128) {
            float c = sigm(gates[128 + tid]) * cc[tid] + sigm(gates[tid]) * tanhf(gates[256 + tid]);
            cc[tid] = c;
            hh[tid] = sigm(gates[384 + tid]) * tanhf(c);
        }
        __syncthreads();
        float mloc = -INFINITY;
        float4 h4 = *(float4*)&hh[4 * lane];
        for (int n = lo + w; n < hi; n += 8) {
            float4 a4 = *(const float4*)(nf + (size_t)n * 128 + 4 * lane);
            float t = a4.x * h4.x + a4.y * h4.y + a4.z * h4.z + a4.w * h4.w;
#pragma unroll
            for (int o = 16; o; o >>= 1) t += __shfl_xor_sync(0xffffffffu, t, o);
            if (lane == 0) ener[n] = t;
            mloc = fmaxf(mloc, t);
        }
#pragma unroll
        for (int o = 16; o; o >>= 1) mloc = fmaxf(mloc, __shfl_xor_sync(0xffffffffu, mloc, o));
        if (lane == 0) red[w] = mloc;
        __syncthreads();
        if (tid == 0) {
            float m = -INFINITY;
            for (int i = 0; i < 8; i++) m = fmaxf(m, red[i]);
            red[8] = m;
        }
        __syncthreads();
        float m = red[8];
        float dloc = 0.f;
        for (int n = lo + tid; n < hi; n += 256) dloc += expf(ener[n] - m);
#pragma unroll
        for (int o = 16; o; o >>= 1) dloc += __shfl_xor_sync(0xffffffffu, dloc, o);
        __syncthreads();
        if (lane == 0) red[w] = dloc;
        __syncthreads();
        if (tid == 0) {
            float d = 0.f;
            for (int i = 0; i < 8; i++) d += red[i];
            red[9] = d;
        }
        __syncthreads();
        float invd = 1.f / red[9];
        float4 racc = make_float4(0.f, 0.f, 0.f, 0.f);
        for (int n = lo + w; n < hi; n += 8) {
            float coef = expf(ener[n] - m) * invd;
            float4 a4 = *(const float4*)(nf + (size_t)n * 128 + 4 * lane);
            racc.x += coef * a4.x; racc.y += coef * a4.y;
            racc.z += coef * a4.z; racc.w += coef * a4.w;
        }
        *(float4*)&rsh[w * 128 + 4 * lane] = racc;
        __syncthreads();
        if (tid < 128) {
            float ro = 0.f;
#pragma unroll
            for (int i = 0; i < 8; i++) ro += rsh[i * 128 + tid];
            qs[tid] = hh[tid];
            qs[128 + tid] = ro;
        }
        __syncthreads();
    }
    out[(size_t)g * 256 + tid] = qs[tid];
}

// ---------------- launch ----------------
extern "C" void kernel_launch(void* const* d_in, const int* in_sizes, int n_in,
                              void* d_out, int out_size) {
    const float* node = (const float*)d_in[0];
    const float* edge = (const float*)d_in[1];
    const float* Wq = (const float*)d_in[2];
    const float* Wk = (const float*)d_in[3];
    const float* Wv = (const float*)d_in[4];
    const float* We = (const float*)d_in[5];
    const float* Wo = (const float*)d_in[6];
    const float* bo = (const float*)d_in[7];
    const float* W1 = (const float*)d_in[8];
    const float* W2 = (const float*)d_in[9];
    const float* l1nw = (const float*)d_in[10];
    const float* l1nb = (const float*)d_in[11];
    const float* l1ew = (const float*)d_in[12];
    const float* l1eb = (const float*)d_in[13];
    const float* l2w = (const float*)d_in[14];
    const float* l2b = (const float*)d_in[15];
    const float* Wih = (const float*)d_in[16];
    const float* Whh = (const float*)d_in[17];
    const float* bih = (const float*)d_in[18];
    const float* bhh = (const float*)d_in[19];
    const int* src = (const int*)d_in[20];
    const int* dst = (const int*)d_in[21];
    const int* gid = (const int*)d_in[22];

    int N = in_sizes[0] / 128;
    int E = in_sizes[20];
    int G = out_size / 256;

    float *b1, *q, *k, *v, *x, *wv, *z, *t, *en;
    cudaGetSymbolAddress((void**)&b1, g_b1);
    cudaGetSymbolAddress((void**)&q,  g_Q);
    cudaGetSymbolAddress((void**)&k,  g_K);
    cudaGetSymbolAddress((void**)&v,  g_V);
    cudaGetSymbolAddress((void**)&x,  g_x);
    cudaGetSymbolAddress((void**)&wv, g_wV);
    cudaGetSymbolAddress((void**)&z,  g_z);
    cudaGetSymbolAddress((void**)&t,  g_t);
    cudaGetSymbolAddress((void**)&en, g_en);

    cudaFuncSetAttribute(edge_kernel, cudaFuncAttributeMaxDynamicSharedMemorySize, EDGE_SMEM);
    cudaFuncSetAttribute(qkv_kernel, cudaFuncAttributeMaxDynamicSharedMemorySize, GEMM_SMEM);
    cudaFuncSetAttribute(gemm_kernel<1>, cudaFuncAttributeMaxDynamicSharedMemorySize, GEMM_SMEM);
    cudaFuncSetAttribute(gemm_kernel<2>, cudaFuncAttributeMaxDynamicSharedMemorySize, GEMM_SMEM);
    cudaFuncSetAttribute(gemm_kernel<3>, cudaFuncAttributeMaxDynamicSharedMemorySize, GEMM_SMEM);

    int gnodes = (N + 127) / 128;

    ln_kernel<<<(N + 7) / 8, 256>>>(node, b1, l1nw, l1nb, N);
    qkv_kernel<<<dim3(gnodes, 3), 256, GEMM_SMEM>>>(b1, Wq, Wk, Wv, q, k, v, N);
    fzero2_kernel<<<(N * 33 + 255) / 256, 256>>>((float4*)wv, (float4*)z, N * 32, N);
    edge_kernel<<<(E + 127) / 128, 256, EDGE_SMEM>>>(edge, l1ew, l1eb, We, src, dst,
                                                     q, k, v, wv, z, E);
    attn_kernel<<<(N * 32 + 255) / 256, 256>>>(wv, z, b1, N);
    gemm_kernel<1><<<dim3(gnodes, 1), 256, GEMM_SMEM>>>(b1, Wo, bo, node, x, N, 128, 128);
    ln_kernel<<<(N + 7) / 8, 256>>>(x, q, l2w, l2b, N);
    gemm_kernel<2><<<dim3(gnodes, 2), 256, GEMM_SMEM>>>(q, W1, nullptr, nullptr, t, N, 128, 256);
    gemm_kernel<3><<<dim3(gnodes, 1), 256, GEMM_SMEM>>>(t, W2, nullptr, x, k, N, 256, 128);
    set2set_kernel<<<G, 256>>>(k, gid, Wih, Whh, bih, bhh, en, (float*)d_out, N);
}

// round 14
// speedup vs baseline: 1.5903x; 1.0214x over previous
#include <cuda_runtime.h>
#include <math.h>
#include <stdint.h>

#define MAXN 50048
#define MAXE 600064

// ---------------- scratch (static device globals; no allocation) ----------------
__device__ float g_b1[(size_t)MAXN * 128];
__device__ float g_Q [(size_t)MAXN * 128];
__device__ float g_K [(size_t)MAXN * 128];
__device__ float g_V [(size_t)MAXN * 128];
__device__ float g_x [(size_t)MAXN * 128];
__device__ float g_wV[(size_t)MAXN * 128];
__device__ float g_z [(size_t)MAXN * 4];
__device__ float g_t [(size_t)MAXN * 256];
__device__ float g_en[(size_t)MAXN];
// pre-split weight planes: [Wq|Wk|Wv|We|Wo|W1|W2] = 5*16384 + 32768 + 32768 = 147456 floats
__device__ float g_wh[147456];
__device__ float g_wl[147456];
#define OFF_WQ 0
#define OFF_WK 16384
#define OFF_WV 32768
#define OFF_WE 49152
#define OFF_WO 65536
#define OFF_W1 81920
#define OFF_W2 114688
#define W_TOTAL4 36864   // 147456 / 4

__device__ __forceinline__ float clip5(float x) { return fminf(fmaxf(x, -5.f), 5.f); }
__device__ __forceinline__ float sigm(float x)  { return 1.f / (1.f + expf(-x)); }

__device__ __forceinline__ void red_add_v4(float* p, float a, float b, float c, float d) {
    asm volatile("red.global.add.v4.f32 [%0], {%1,%2,%3,%4};"
                 :: "l"(p), "f"(a), "f"(b), "f"(c), "f"(d) : "memory");
}
__device__ __forceinline__ void red_add_f(float* p, float v) {
    asm volatile("red.global.add.f32 [%0], %1;" :: "l"(p), "f"(v) : "memory");
}

// ---- TF32 helpers ----
__device__ __forceinline__ void tf32split(float x, float& hi, float& lo) {
    uint32_t h; asm("cvt.rna.tf32.f32 %0, %1;" : "=r"(h) : "f"(x));
    float hf = __uint_as_float(h);
    float l = x - hf;
    uint32_t lr; asm("cvt.rna.tf32.f32 %0, %1;" : "=r"(lr) : "f"(l));
    hi = hf; lo = __uint_as_float(lr);
}
__device__ __forceinline__ float tf32r(float x) {
    uint32_t h; asm("cvt.rna.tf32.f32 %0, %1;" : "=r"(h) : "f"(x));
    return __uint_as_float(h);
}
__device__ __forceinline__ void mma8(float* d, const uint32_t* a, uint32_t b0, uint32_t b1) {
    asm volatile("mma.sync.aligned.m16n8k8.row.col.f32.tf32.tf32.f32 "
        "{%0,%1,%2,%3}, {%4,%5,%6,%7}, {%8,%9}, {%0,%1,%2,%3};"
        : "+f"(d[0]), "+f"(d[1]), "+f"(d[2]), "+f"(d[3])
        : "r"(a[0]), "r"(a[1]), "r"(a[2]), "r"(a[3]), "r"(b0), "r"(b1));
}

// ---------------- prep kernel: zero wV/z AND split all weights into hi/lo ------------
__global__ void prep_kernel(float4* __restrict__ wv, float4* __restrict__ z,
                            int nwv4, int nz4,
                            const float* __restrict__ Wq, const float* __restrict__ Wk,
                            const float* __restrict__ Wvv, const float* __restrict__ We,
                            const float* __restrict__ Wo, const float* __restrict__ W1,
                            const float* __restrict__ W2,
                            float* __restrict__ wh, float* __restrict__ wl) {
    int i = blockIdx.x * blockDim.x + threadIdx.x;
    if (i < nwv4) { wv[i] = make_float4(0.f, 0.f, 0.f, 0.f); return; }
    int j = i - nwv4;
    if (j < nz4) { z[j] = make_float4(0.f, 0.f, 0.f, 0.f); return; }
    int e4 = j - nz4;
    if (e4 >= W_TOTAL4) return;
    int e = e4 * 4;
    const float* src; int off;
    if      (e < OFF_WK) { src = Wq;  off = e - OFF_WQ; }
    else if (e < OFF_WV) { src = Wk;  off = e - OFF_WK; }
    else if (e < OFF_WE) { src = Wvv; off = e - OFF_WV; }
    else if (e < OFF_WO) { src = We;  off = e - OFF_WE; }
    else if (e < OFF_W1) { src = Wo;  off = e - OFF_WO; }
    else if (e < OFF_W2) { src = W1;  off = e - OFF_W1; }
    else                 { src = W2;  off = e - OFF_W2; }
    float4 v = *(const float4*)(src + off);
    float4 hv, lv;
    tf32split(v.x, hv.x, lv.x);
    tf32split(v.y, hv.y, lv.y);
    tf32split(v.z, hv.z, lv.z);
    tf32split(v.w, hv.w, lv.w);
    *(float4*)(wh + e) = hv;
    *(float4*)(wl + e) = lv;
}

// ---------------- row LayerNorm (warp per 128-wide row) ----------------
__global__ void ln_kernel(const float* __restrict__ in, float* __restrict__ out,
                          const float* __restrict__ w, const float* __restrict__ b, int rows) {
    int warp = (blockIdx.x * blockDim.x + threadIdx.x) >> 5;
    int lane = threadIdx.x & 31;
    if (warp >= rows) return;
    float4 v = *(const float4*)(in + (size_t)warp * 128 + 4 * lane);
    float s  = v.x + v.y + v.z + v.w;
    float sq = v.x * v.x + v.y * v.y + v.z * v.z + v.w * v.w;
#pragma unroll
    for (int o = 16; o; o >>= 1) {
        s  += __shfl_xor_sync(0xffffffffu, s,  o);
        sq += __shfl_xor_sync(0xffffffffu, sq, o);
    }
    float mu   = s * (1.f / 128.f);
    float rstd = rsqrtf(sq * (1.f / 128.f) - mu * mu + 1e-5f);
    float4 wv = *(const float4*)(w + 4 * lane);
    float4 bv = *(const float4*)(b + 4 * lane);
    float4 o4;
    o4.x = (v.x - mu) * rstd * wv.x + bv.x;
    o4.y = (v.y - mu) * rstd * wv.y + bv.y;
    o4.z = (v.z - mu) * rstd * wv.z + bv.z;
    o4.w = (v.w - mu) * rstd * wv.w + bv.w;
    *(float4*)(out + (size_t)warp * 128 + 4 * lane) = o4;
}

// ---------------- tensor GEMM body: 128x128, A 2xTF32, pre-split W planes -------------
// DIVZ: A = A_raw * 1/(z[row*4+kt]+1e-6) at staging (K must be 128; head==kt)
#define AS 36
#define WS 136
template <int EPI, int DIVZ>
__device__ __forceinline__ void gemm_body(
    const float* __restrict__ A, const float* __restrict__ Wh, const float* __restrict__ Wl,
    const float* __restrict__ bias, const float* __restrict__ res, const float* __restrict__ zp,
    float* __restrict__ C, int M, int K, int NC, int row0, int cb,
    float* A_sh, float* Whi, float* Wlo) {
    int tid = threadIdx.x;
    int lane = tid & 31, wid = tid >> 5;
    int wm = wid >> 1, wn = wid & 1;
    int g = lane >> 2, t = lane & 3;
    float acc[2][8][4];
#pragma unroll
    for (int mf = 0; mf < 2; mf++)
#pragma unroll
        for (int nf = 0; nf < 8; nf++)
#pragma unroll
            for (int u = 0; u < 4; u++) acc[mf][nf][u] = 0.f;

    int nkt = K >> 5;
    for (int kt = 0; kt < nkt; ++kt) {
#pragma unroll
        for (int it = 0; it < 4; ++it) {   // A chunk 128x32, tf32-rounded
            int idx = tid + it * 256;
            int r = idx >> 3, c4 = (idx & 7) << 2;
            float4 v = make_float4(0.f, 0.f, 0.f, 0.f);
            if (row0 + r < M) {
                v = *(const float4*)(A + (size_t)(row0 + r) * K + kt * 32 + c4);
                if (DIVZ) {
                    float invz = 1.f / (zp[(size_t)(row0 + r) * 4 + kt] + 1e-6f);
                    v.x *= invz; v.y *= invz; v.z *= invz; v.w *= invz;
                }
            }
            v.x = tf32r(v.x); v.y = tf32r(v.y); v.z = tf32r(v.z); v.w = tf32r(v.w);
            *(float4*)(A_sh + r * AS + c4) = v;
        }
#pragma unroll
        for (int it = 0; it < 4; ++it) {   // W chunk 32x128 — pre-split planes, pure copy
            int idx = tid + it * 256;
            int kk = idx >> 5, wc = (idx & 31) << 2;
            size_t go = (size_t)(kt * 32 + kk) * NC + cb + wc;
            *(float4*)(Whi + kk * WS + wc) = *(const float4*)(Wh + go);
            *(float4*)(Wlo + kk * WS + wc) = *(const float4*)(Wl + go);
        }
        __syncthreads();
#pragma unroll
        for (int k8 = 0; k8 < 4; ++k8) {
            int ck = k8 * 8;
            uint32_t a[2][4];
#pragma unroll
            for (int mf = 0; mf < 2; ++mf) {
                int rb = 32 * wm + 16 * mf;
                a[mf][0] = __float_as_uint(A_sh[(rb + g)     * AS + ck + t]);
                a[mf][1] = __float_as_uint(A_sh[(rb + g + 8) * AS + ck + t]);
                a[mf][2] = __float_as_uint(A_sh[(rb + g)     * AS + ck + t + 4]);
                a[mf][3] = __float_as_uint(A_sh[(rb + g + 8) * AS + ck + t + 4]);
            }
#pragma unroll
            for (int nf = 0; nf < 8; ++nf) {
                int nb = 64 * wn + 8 * nf + g;
                uint32_t bh0 = __float_as_uint(Whi[(ck + t)     * WS + nb]);
                uint32_t bh1 = __float_as_uint(Whi[(ck + t + 4) * WS + nb]);
                uint32_t bl0 = __float_as_uint(Wlo[(ck + t)     * WS + nb]);
                uint32_t bl1 = __float_as_uint(Wlo[(ck + t + 4) * WS + nb]);
#pragma unroll
                for (int mf = 0; mf < 2; ++mf) {
                    mma8(acc[mf][nf], a[mf], bl0, bl1);
                    mma8(acc[mf][nf], a[mf], bh0, bh1);
                }
            }
        }
        __syncthreads();
    }
#pragma unroll
    for (int mf = 0; mf < 2; ++mf) {
#pragma unroll
        for (int nf = 0; nf < 8; ++nf) {
            int c  = cb + 64 * wn + 8 * nf + 2 * t;
            int r0 = row0 + 32 * wm + 16 * mf + g;
            float2 v0 = make_float2(acc[mf][nf][0], acc[mf][nf][1]);
            float2 v1 = make_float2(acc[mf][nf][2], acc[mf][nf][3]);
            if (EPI == 2) {
                v0.x = v0.x / (1.f + expf(-v0.x)); v0.y = v0.y / (1.f + expf(-v0.y));
                v1.x = v1.x / (1.f + expf(-v1.x)); v1.y = v1.y / (1.f + expf(-v1.y));
            }
            if (r0 < M) {
                if (EPI == 1) {
                    float2 b = *(const float2*)(bias + c);
                    float2 rr = *(const float2*)(res + (size_t)r0 * NC + c);
                    v0.x += b.x + rr.x; v0.y += b.y + rr.y;
                }
                if (EPI == 3) {
                    float2 rr = *(const float2*)(res + (size_t)r0 * NC + c);
                    v0.x += rr.x; v0.y += rr.y;
                }
                *(float2*)(C + (size_t)r0 * NC + c) = v0;
            }
            int r1 = r0 + 8;
            if (r1 < M) {
                if (EPI == 1) {
                    float2 b = *(const float2*)(bias + c);
                    float2 rr = *(const float2*)(res + (size_t)r1 * NC + c);
                    v1.x += b.x + rr.x; v1.y += b.y + rr.y;
                }
                if (EPI == 3) {
                    float2 rr = *(const float2*)(res + (size_t)r1 * NC + c);
                    v1.x += rr.x; v1.y += rr.y;
                }
                *(float2*)(C + (size_t)r1 * NC + c) = v1;
            }
        }
    }
}

#define GEMM_SMEM ((128 * AS + 2 * 32 * WS) * 4)

template <int EPI, int DIVZ>
__global__ void __launch_bounds__(256, 2) gemm_kernel(
    const float* __restrict__ A, const float* __restrict__ Wh, const float* __restrict__ Wl,
    const float* __restrict__ bias, const float* __restrict__ res, const float* __restrict__ zp,
    float* __restrict__ C, int M, int K, int NC) {
    extern __shared__ float gsh[];
    float* A_sh = gsh;
    float* Whi  = gsh + 128 * AS;
    float* Wlo  = Whi + 32 * WS;
    gemm_body<EPI, DIVZ>(A, Wh, Wl, bias, res, zp, C, M, K, NC,
                         blockIdx.x * 128, blockIdx.y * 128, A_sh, Whi, Wlo);
}

__global__ void __launch_bounds__(256, 2) qkv_kernel(
    const float* __restrict__ A, const float* __restrict__ wh, const float* __restrict__ wl,
    float* __restrict__ Q, float* __restrict__ Ko, float* __restrict__ V, int M) {
    extern __shared__ float gsh[];
    float* A_sh = gsh;
    float* Whi  = gsh + 128 * AS;
    float* Wlo  = Whi + 32 * WS;
    int off = (blockIdx.y == 0) ? OFF_WQ : (blockIdx.y == 1) ? OFF_WK : OFF_WV;
    float* C  = (blockIdx.y == 0) ? Q : (blockIdx.y == 1) ? Ko : V;
    gemm_body<0, 0>(A, wh + off, wl + off, nullptr, nullptr, nullptr, C, M, 128, 128,
                    blockIdx.x * 128, 0, A_sh, Whi, Wlo);
}

// ---------------- fused edge kernel: LN -> Pe GEMM (A 2xTF32, pre-split We) -> scatter --
#define LN_STRIDE 132
__global__ void __launch_bounds__(256, 2) edge_kernel(
    const float* __restrict__ ef, const float* __restrict__ lnw, const float* __restrict__ lnb,
    const float* __restrict__ Weh, const float* __restrict__ Wel,
    const int* __restrict__ src, const int* __restrict__ dst,
    const float* __restrict__ Q, const float* __restrict__ Kv, const float* __restrict__ V,
    float* __restrict__ wV, float* __restrict__ z, int E) {
    extern __shared__ float sh[];
    float* LN_sh = sh;
    float* Whi   = sh + 128 * LN_STRIDE;
    float* Wlo   = Whi + 32 * WS;
    int* s_sh = (int*)(Wlo + 32 * WS);
    int* d_sh = s_sh + 128;

    int tid = threadIdx.x, lane = tid & 31, w = tid >> 5;
    int e0 = blockIdx.x * 128;
    if (tid < 128) {
        int e = e0 + tid;
        s_sh[tid] = (e < E) ? src[e] : 0;
        d_sh[tid] = (e < E) ? dst[e] : 0;
    }
    float4 lw = *(const float4*)(lnw + 4 * lane);
    float4 lb = *(const float4*)(lnb + 4 * lane);
#pragma unroll
    for (int i = 0; i < 16; i++) {
        int r = w * 16 + i;
        int e = e0 + r;
        float4 v = make_float4(0.f, 0.f, 0.f, 0.f);
        if (e < E) v = *(const float4*)(ef + (size_t)e * 128 + 4 * lane);
        float s  = v.x + v.y + v.z + v.w;
        float sq = v.x * v.x + v.y * v.y + v.z * v.z + v.w * v.w;
#pragma unroll
        for (int o = 16; o; o >>= 1) {
            s  += __shfl_xor_sync(0xffffffffu, s,  o);
            sq += __shfl_xor_sync(0xffffffffu, sq, o);
        }
        float mu   = s * (1.f / 128.f);
        float rstd = rsqrtf(sq * (1.f / 128.f) - mu * mu + 1e-5f);
        float4 o4;
        o4.x = tf32r((v.x - mu) * rstd * lw.x + lb.x);
        o4.y = tf32r((v.y - mu) * rstd * lw.y + lb.y);
        o4.z = tf32r((v.z - mu) * rstd * lw.z + lb.z);
        o4.w = tf32r((v.w - mu) * rstd * lw.w + lb.w);
        *(float4*)(LN_sh + r * LN_STRIDE + 4 * lane) = o4;
    }
    __syncthreads();
    int wm = w >> 1, wn = w & 1;
    int g = lane >> 2, t = lane & 3;
    float acc[2][8][4];
#pragma unroll
    for (int mf = 0; mf < 2; mf++)
#pragma unroll
        for (int nf = 0; nf < 8; nf++)
#pragma unroll
            for (int u = 0; u < 4; u++) acc[mf][nf][u] = 0.f;
    for (int kt = 0; kt < 4; ++kt) {
#pragma unroll
        for (int it = 0; it < 4; ++it) {
            int idx = tid + it * 256;
            int kk = idx >> 5, wc = (idx & 31) << 2;
            size_t go = (size_t)(kt * 32 + kk) * 128 + wc;
            *(float4*)(Whi + kk * WS + wc) = *(const float4*)(Weh + go);
            *(float4*)(Wlo + kk * WS + wc) = *(const float4*)(Wel + go);
        }
        __syncthreads();
#pragma unroll
        for (int k8 = 0; k8 < 4; ++k8) {
            int ckA = kt * 32 + k8 * 8;
            int ckW = k8 * 8;
            uint32_t a[2][4];
#pragma unroll
            for (int mf = 0; mf < 2; ++mf) {
                int rb = 32 * wm + 16 * mf;
                a[mf][0] = __float_as_uint(LN_sh[(rb + g)     * LN_STRIDE + ckA + t]);
                a[mf][1] = __float_as_uint(LN_sh[(rb + g + 8) * LN_STRIDE + ckA + t]);
                a[mf][2] = __float_as_uint(LN_sh[(rb + g)     * LN_STRIDE + ckA + t + 4]);
                a[mf][3] = __float_as_uint(LN_sh[(rb + g + 8) * LN_STRIDE + ckA + t + 4]);
            }
#pragma unroll
            for (int nf = 0; nf < 8; ++nf) {
                int nb = 64 * wn + 8 * nf + g;
                uint32_t bh0 = __float_as_uint(Whi[(ckW + t)     * WS + nb]);
                uint32_t bh1 = __float_as_uint(Whi[(ckW + t + 4) * WS + nb]);
                uint32_t bl0 = __float_as_uint(Wlo[(ckW + t)     * WS + nb]);
                uint32_t bl1 = __float_as_uint(Wlo[(ckW + t + 4) * WS + nb]);
#pragma unroll
                for (int mf = 0; mf < 2; ++mf) {
                    mma8(acc[mf][nf], a[mf], bl0, bl1);
                    mma8(acc[mf][nf], a[mf], bh0, bh1);
                }
            }
        }
        __syncthreads();
    }
#pragma unroll
    for (int mf = 0; mf < 2; ++mf) {
#pragma unroll
        for (int nf = 0; nf < 8; ++nf) {
            int r0 = 32 * wm + 16 * mf + g;
            int c  = 64 * wn + 8 * nf + 2 * t;
            *(float2*)(LN_sh + r0 * LN_STRIDE + c)       = make_float2(acc[mf][nf][0], acc[mf][nf][1]);
            *(float2*)(LN_sh + (r0 + 8) * LN_STRIDE + c) = make_float2(acc[mf][nf][2], acc[mf][nf][3]);
        }
    }
    __syncthreads();
    const float inv = 0.17677669529663687f;
    int head = lane >> 3;
    int base = w * 16;
    int si = s_sh[base], di = d_sh[base];
    float4 kq = *(const float4*)(Kv + (size_t)si * 128 + 4 * lane);
    float4 qv = *(const float4*)(Q  + (size_t)di * 128 + 4 * lane);
    float4 vv = *(const float4*)(V  + (size_t)si * 128 + 4 * lane);
#pragma unroll
    for (int j = 0; j < 16; j++) {
        int e = e0 + base + j;
        float4 kqc = kq, qvc = qv, vvc = vv;
        int dic = di;
        if (j < 15) {
            int sn = s_sh[base + j + 1], dn = d_sh[base + j + 1];
            kq = *(const float4*)(Kv + (size_t)sn * 128 + 4 * lane);
            qv = *(const float4*)(Q  + (size_t)dn * 128 + 4 * lane);
            vv = *(const float4*)(V  + (size_t)sn * 128 + 4 * lane);
            di = dn;
        }
        if (e < E) {
            float4 pe = *(float4*)(LN_sh + (base + j) * LN_STRIDE + 4 * lane);
            float tt = clip5(kqc.x * qvc.x * inv) * pe.x + clip5(kqc.y * qvc.y * inv) * pe.y
                     + clip5(kqc.z * qvc.z * inv) * pe.z + clip5(kqc.w * qvc.w * inv) * pe.w;
            tt += __shfl_xor_sync(0xffffffffu, tt, 1);
            tt += __shfl_xor_sync(0xffffffffu, tt, 2);
            tt += __shfl_xor_sync(0xffffffffu, tt, 4);
            float s = expf(clip5(tt));
            float* dp = wV + (size_t)dic * 128 + 4 * lane;
            red_add_v4(dp, vvc.x * s, vvc.y * s, vvc.z * s, vvc.w * s);
            if ((lane & 7) == 0) red_add_f(z + (size_t)dic * 4 + head, s);
        }
    }
}
#define EDGE_SMEM ((128 * LN_STRIDE + 2 * 32 * WS) * 4 + 2 * 128 * 4)

// ---------------- Set2Set: one block (512 threads) per graph --------------------------
__global__ void __launch_bounds__(512) set2set_kernel(
    const float* __restrict__ nf, const int* __restrict__ gid,
    const float* __restrict__ W_ih, const float* __restrict__ W_hh,
    const float* __restrict__ b_ih, const float* __restrict__ b_hh,
    float* __restrict__ ener, float* __restrict__ out, int N) {
    __shared__ float qs[256], hh[128], cc[128], gates[512], rsh[16 * 128], red[34];
    int tid = threadIdx.x, lane = tid & 31, w = tid >> 5;   // w in [0,16)
    int g = blockIdx.x;
    int lo, hi;
    {
        int a = 0, b = N;
        while (a < b) { int m = (a + b) >> 1; if (gid[m] < g) a = m + 1; else b = m; }
        lo = a;
        b = N;
        while (a < b) { int m = (a + b) >> 1; if (gid[m] < g + 1) a = m + 1; else b = m; }
        hi = a;
    }
    if (tid < 256) qs[tid] = 0.f;
    if (tid < 128) { hh[tid] = 0.f; cc[tid] = 0.f; }
    __syncthreads();

    for (int it = 0; it < 3; ++it) {
        {   // one gate per thread
            int j = tid;
            float acc = b_ih[j] + b_hh[j];
            const float* wi = W_ih + (size_t)j * 256;
#pragma unroll 8
            for (int k2 = 0; k2 < 256; k2++) acc += qs[k2] * wi[k2];
            const float* whp = W_hh + (size_t)j * 128;
#pragma unroll 8
            for (int k2 = 0; k2 < 128; k2++) acc += hh[k2] * whp[k2];
            gates[j] = acc;
        }
        __syncthreads();
        if (tid < 128) {
            float c = sigm(gates[128 + tid]) * cc[tid] + sigm(gates[tid]) * tanhf(gates[256 + tid]);
            cc[tid] = c;
            hh[tid] = sigm(gates[384 + tid]) * tanhf(c);
        }
        __syncthreads();
        float mloc = -INFINITY;
        float4 h4 = *(float4*)&hh[4 * lane];
        for (int n = lo + w; n < hi; n += 16) {
            float4 a4 = *(const float4*)(nf + (size_t)n * 128 + 4 * lane);
            float t = a4.x * h4.x + a4.y * h4.y + a4.z * h4.z + a4.w * h4.w;
#pragma unroll
            for (int o = 16; o; o >>= 1) t += __shfl_xor_sync(0xffffffffu, t, o);
            if (lane == 0) ener[n] = t;
            mloc = fmaxf(mloc, t);
        }
#pragma unroll
        for (int o = 16; o; o >>= 1) mloc = fmaxf(mloc, __shfl_xor_sync(0xffffffffu, mloc, o));
        if (lane == 0) red[w] = mloc;
        __syncthreads();
        if (tid == 0) {
            float m = -INFINITY;
            for (int i = 0; i < 16; i++) m = fmaxf(m, red[i]);
            red[32] = m;
        }
        __syncthreads();
        float m = red[32];
        float dloc = 0.f;
        for (int n = lo + tid; n < hi; n += 512) dloc += expf(ener[n] - m);
#pragma unroll
        for (int o = 16; o; o >>= 1) dloc += __shfl_xor_sync(0xffffffffu, dloc, o);
        __syncthreads();
        if (lane == 0) red[w] = dloc;
        __syncthreads();
        if (tid == 0) {
            float d = 0.f;
            for (int i = 0; i < 16; i++) d += red[i];
            red[33] = d;
        }
        __syncthreads();
        float invd = 1.f / red[33];
        float4 racc = make_float4(0.f, 0.f, 0.f, 0.f);
        for (int n = lo + w; n < hi; n += 16) {
            float coef = expf(ener[n] - m) * invd;
            float4 a4 = *(const float4*)(nf + (size_t)n * 128 + 4 * lane);
            racc.x += coef * a4.x; racc.y += coef * a4.y;
            racc.z += coef * a4.z; racc.w += coef * a4.w;
        }
        *(float4*)&rsh[w * 128 + 4 * lane] = racc;
        __syncthreads();
        if (tid < 128) {
            float ro = 0.f;
#pragma unroll
            for (int i = 0; i < 16; i++) ro += rsh[i * 128 + tid];
            qs[tid] = hh[tid];
            qs[128 + tid] = ro;
        }
        __syncthreads();
    }
    if (tid < 256) out[(size_t)g * 256 + tid] = qs[tid];
}

// ---------------- launch ----------------
extern "C" void kernel_launch(void* const* d_in, const int* in_sizes, int n_in,
                              void* d_out, int out_size) {
    const float* node = (const float*)d_in[0];
    const float* edge = (const float*)d_in[1];
    const float* Wq = (const float*)d_in[2];
    const float* Wk = (const float*)d_in[3];
    const float* Wv = (const float*)d_in[4];
    const float* We = (const float*)d_in[5];
    const float* Wo = (const float*)d_in[6];
    const float* bo = (const float*)d_in[7];
    const float* W1 = (const float*)d_in[8];
    const float* W2 = (const float*)d_in[9];
    const float* l1nw = (const float*)d_in[10];
    const float* l1nb = (const float*)d_in[11];
    const float* l1ew = (const float*)d_in[12];
    const float* l1eb = (const float*)d_in[13];
    const float* l2w = (const float*)d_in[14];
    const float* l2b = (const float*)d_in[15];
    const float* Wih = (const float*)d_in[16];
    const float* Whh = (const float*)d_in[17];
    const float* bih = (const float*)d_in[18];
    const float* bhh = (const float*)d_in[19];
    const int* src = (const int*)d_in[20];
    const int* dst = (const int*)d_in[21];
    const int* gid = (const int*)d_in[22];

    int N = in_sizes[0] / 128;
    int E = in_sizes[20];
    int G = out_size / 256;

    float *b1, *q, *k, *v, *x, *wv, *z, *t, *en, *wh, *wl;
    cudaGetSymbolAddress((void**)&b1, g_b1);
    cudaGetSymbolAddress((void**)&q,  g_Q);
    cudaGetSymbolAddress((void**)&k,  g_K);
    cudaGetSymbolAddress((void**)&v,  g_V);
    cudaGetSymbolAddress((void**)&x,  g_x);
    cudaGetSymbolAddress((void**)&wv, g_wV);
    cudaGetSymbolAddress((void**)&z,  g_z);
    cudaGetSymbolAddress((void**)&t,  g_t);
    cudaGetSymbolAddress((void**)&en, g_en);
    cudaGetSymbolAddress((void**)&wh, g_wh);
    cudaGetSymbolAddress((void**)&wl, g_wl);

    cudaFuncSetAttribute(edge_kernel, cudaFuncAttributeMaxDynamicSharedMemorySize, EDGE_SMEM);
    cudaFuncSetAttribute(qkv_kernel, cudaFuncAttributeMaxDynamicSharedMemorySize, GEMM_SMEM);
    cudaFuncSetAttribute((const void*)gemm_kernel<1, 1>, cudaFuncAttributeMaxDynamicSharedMemorySize, GEMM_SMEM);
    cudaFuncSetAttribute((const void*)gemm_kernel<2, 0>, cudaFuncAttributeMaxDynamicSharedMemorySize, GEMM_SMEM);
    cudaFuncSetAttribute((const void*)gemm_kernel<3, 0>, cudaFuncAttributeMaxDynamicSharedMemorySize, GEMM_SMEM);

    int gnodes = (N + 127) / 128;
    int prep_threads = N * 33 + W_TOTAL4;

    // 1) prep: zero wV/z + split all weights
    prep_kernel<<<(prep_threads + 255) / 256, 256>>>((float4*)wv, (float4*)z, N * 32, N,
                                                     Wq, Wk, Wv, We, Wo, W1, W2, wh, wl);
    // 2) LN(node) -> b1
    ln_kernel<<<(N + 7) / 8, 256>>>(node, b1, l1nw, l1nb, N);
    // 3) Q, K, V
    qkv_kernel<<<dim3(gnodes, 3), 256, GEMM_SMEM>>>(b1, wh, wl, q, k, v, N);
    // 4) fused edge kernel
    edge_kernel<<<(E + 127) / 128, 256, EDGE_SMEM>>>(edge, l1ew, l1eb, wh + OFF_WE, wl + OFF_WE,
                                                     src, dst, q, k, v, wv, z, E);
    // 5) x = node + (wV/z)@Wo + bo   (attn divide folded into A staging)
    gemm_kernel<1, 1><<<dim3(gnodes, 1), 256, GEMM_SMEM>>>(wv, wh + OFF_WO, wl + OFF_WO,
                                                           bo, node, z, x, N, 128, 128);
    // 6) y = LN2(x) -> q
    ln_kernel<<<(N + 7) / 8, 256>>>(x, q, l2w, l2b, N);
    // 7) t = silu(y @ W1)
    gemm_kernel<2, 0><<<dim3(gnodes, 2), 256, GEMM_SMEM>>>(q, wh + OFF_W1, wl + OFF_W1,
                                                           nullptr, nullptr, nullptr, t, N, 128, 256);
    // 8) nf = x + t @ W2 -> k
    gemm_kernel<3, 0><<<dim3(gnodes, 1), 256, GEMM_SMEM>>>(t, wh + OFF_W2, wl + OFF_W2,
                                                           nullptr, x, nullptr, k, N, 256, 128);
    // 9) Set2Set readout (512 threads/graph)
    set2set_kernel<<<G, 512>>>(k, gid, Wih, Whh, bih, bhh, en, (float*)d_out, N);
}

// round 17
// speedup vs baseline: 1.6168x; 1.0166x over previous
#include <cuda_runtime.h>
#include <math.h>
#include <stdint.h>

#define MAXN 50048
#define MAXE 600064

// ---------------- scratch (static device globals; no allocation) ----------------
__device__ float g_b1[(size_t)MAXN * 128];
__device__ float g_Q [(size_t)MAXN * 128];
__device__ float g_K [(size_t)MAXN * 128];
__device__ float g_V [(size_t)MAXN * 128];
__device__ float g_x [(size_t)MAXN * 128];
__device__ float g_wV[(size_t)MAXN * 128];
__device__ float g_z [(size_t)MAXN * 4];
__device__ float g_t [(size_t)MAXN * 256];
__device__ float g_en[(size_t)MAXN];
// pre-split weight planes: [Wq|Wk|Wv|We|Wo|W1|W2]
__device__ float g_wh[147456];
__device__ float g_wl[147456];
#define OFF_WQ 0
#define OFF_WK 16384
#define OFF_WV 32768
#define OFF_WE 49152
#define OFF_WO 65536
#define OFF_W1 81920
#define OFF_W2 114688
#define W_TOTAL4 36864

__device__ __forceinline__ float clip5(float x) { return fminf(fmaxf(x, -5.f), 5.f); }
__device__ __forceinline__ float sigm(float x)  { return 1.f / (1.f + expf(-x)); }

__device__ __forceinline__ void red_add_v4(float* p, float a, float b, float c, float d) {
    asm volatile("red.global.add.v4.f32 [%0], {%1,%2,%3,%4};"
                 :: "l"(p), "f"(a), "f"(b), "f"(c), "f"(d) : "memory");
}
__device__ __forceinline__ void red_add_f(float* p, float v) {
    asm volatile("red.global.add.f32 [%0], %1;" :: "l"(p), "f"(v) : "memory");
}

// ---- cache-policy loads (createpolicy + cache_hint: the v4-legal form) ----
__device__ __forceinline__ uint64_t mk_stream_policy() {
    uint64_t pol;
    asm("createpolicy.fractional.L2::evict_first.b64 %0, 1.0;" : "=l"(pol));
    return pol;
}
__device__ __forceinline__ uint64_t mk_keep_policy() {
    uint64_t pol;
    asm("createpolicy.fractional.L2::evict_last.b64 %0, 1.0;" : "=l"(pol));
    return pol;
}
__device__ __forceinline__ float4 ldg_pol(const float* p, uint64_t pol) {
    float4 v;
    asm volatile("ld.global.nc.L2::cache_hint.v4.f32 {%0,%1,%2,%3}, [%4], %5;"
        : "=f"(v.x), "=f"(v.y), "=f"(v.z), "=f"(v.w) : "l"(p), "l"(pol));
    return v;
}

// ---- TF32 helpers ----
__device__ __forceinline__ void tf32split(float x, float& hi, float& lo) {
    uint32_t h; asm("cvt.rna.tf32.f32 %0, %1;" : "=r"(h) : "f"(x));
    float hf = __uint_as_float(h);
    float l = x - hf;
    uint32_t lr; asm("cvt.rna.tf32.f32 %0, %1;" : "=r"(lr) : "f"(l));
    hi = hf; lo = __uint_as_float(lr);
}
__device__ __forceinline__ float tf32r(float x) {
    uint32_t h; asm("cvt.rna.tf32.f32 %0, %1;" : "=r"(h) : "f"(x));
    return __uint_as_float(h);
}
__device__ __forceinline__ void mma8(float* d, const uint32_t* a, uint32_t b0, uint32_t b1) {
    asm volatile("mma.sync.aligned.m16n8k8.row.col.f32.tf32.tf32.f32 "
        "{%0,%1,%2,%3}, {%4,%5,%6,%7}, {%8,%9}, {%0,%1,%2,%3};"
        : "+f"(d[0]), "+f"(d[1]), "+f"(d[2]), "+f"(d[3])
        : "r"(a[0]), "r"(a[1]), "r"(a[2]), "r"(a[3]), "r"(b0), "r"(b1));
}

// ---------------- prep kernel: zero wV/z AND split all weights into hi/lo ------------
__global__ void prep_kernel(float4* __restrict__ wv, float4* __restrict__ z,
                            int nwv4, int nz4,
                            const float* __restrict__ Wq, const float* __restrict__ Wk,
                            const float* __restrict__ Wvv, const float* __restrict__ We,
                            const float* __restrict__ Wo, const float* __restrict__ W1,
                            const float* __restrict__ W2,
                            float* __restrict__ wh, float* __restrict__ wl) {
    int i = blockIdx.x * blockDim.x + threadIdx.x;
    if (i < nwv4) { wv[i] = make_float4(0.f, 0.f, 0.f, 0.f); return; }
    int j = i - nwv4;
    if (j < nz4) { z[j] = make_float4(0.f, 0.f, 0.f, 0.f); return; }
    int e4 = j - nz4;
    if (e4 >= W_TOTAL4) return;
    int e = e4 * 4;
    const float* src; int off;
    if      (e < OFF_WK) { src = Wq;  off = e - OFF_WQ; }
    else if (e < OFF_WV) { src = Wk;  off = e - OFF_WK; }
    else if (e < OFF_WE) { src = Wvv; off = e - OFF_WV; }
    else if (e < OFF_WO) { src = We;  off = e - OFF_WE; }
    else if (e < OFF_W1) { src = Wo;  off = e - OFF_WO; }
    else if (e < OFF_W2) { src = W1;  off = e - OFF_W1; }
    else                 { src = W2;  off = e - OFF_W2; }
    float4 v = *(const float4*)(src + off);
    float4 hv, lv;
    tf32split(v.x, hv.x, lv.x);
    tf32split(v.y, hv.y, lv.y);
    tf32split(v.z, hv.z, lv.z);
    tf32split(v.w, hv.w, lv.w);
    *(float4*)(wh + e) = hv;
    *(float4*)(wl + e) = lv;
}

// ---------------- row LayerNorm (warp per 128-wide row) ----------------
__global__ void ln_kernel(const float* __restrict__ in, float* __restrict__ out,
                          const float* __restrict__ w, const float* __restrict__ b, int rows) {
    int warp = (blockIdx.x * blockDim.x + threadIdx.x) >> 5;
    int lane = threadIdx.x & 31;
    if (warp >= rows) return;
    float4 v = *(const float4*)(in + (size_t)warp * 128 + 4 * lane);
    float s  = v.x + v.y + v.z + v.w;
    float sq = v.x * v.x + v.y * v.y + v.z * v.z + v.w * v.w;
#pragma unroll
    for (int o = 16; o; o >>= 1) {
        s  += __shfl_xor_sync(0xffffffffu, s,  o);
        sq += __shfl_xor_sync(0xffffffffu, sq, o);
    }
    float mu   = s * (1.f / 128.f);
    float rstd = rsqrtf(sq * (1.f / 128.f) - mu * mu + 1e-5f);
    float4 wv = *(const float4*)(w + 4 * lane);
    float4 bv = *(const float4*)(b + 4 * lane);
    float4 o4;
    o4.x = (v.x - mu) * rstd * wv.x + bv.x;
    o4.y = (v.y - mu) * rstd * wv.y + bv.y;
    o4.z = (v.z - mu) * rstd * wv.z + bv.z;
    o4.w = (v.w - mu) * rstd * wv.w + bv.w;
    *(float4*)(out + (size_t)warp * 128 + 4 * lane) = o4;
}

// ---------------- tensor GEMM body: 128x128, A 2xTF32, pre-split W planes -------------
#define AS 36
#define WS 136
template <int EPI, int DIVZ>
__device__ __forceinline__ void gemm_body(
    const float* __restrict__ A, const float* __restrict__ Wh, const float* __restrict__ Wl,
    const float* __restrict__ bias, const float* __restrict__ res, const float* __restrict__ zp,
    float* __restrict__ C, int M, int K, int NC, int row0, int cb,
    float* A_sh, float* Whi, float* Wlo) {
    int tid = threadIdx.x;
    int lane = tid & 31, wid = tid >> 5;
    int wm = wid >> 1, wn = wid & 1;
    int g = lane >> 2, t = lane & 3;
    float acc[2][8][4];
#pragma unroll
    for (int mf = 0; mf < 2; mf++)
#pragma unroll
        for (int nf = 0; nf < 8; nf++)
#pragma unroll
            for (int u = 0; u < 4; u++) acc[mf][nf][u] = 0.f;

    int nkt = K >> 5;
    for (int kt = 0; kt < nkt; ++kt) {
#pragma unroll
        for (int it = 0; it < 4; ++it) {
            int idx = tid + it * 256;
            int r = idx >> 3, c4 = (idx & 7) << 2;
            float4 v = make_float4(0.f, 0.f, 0.f, 0.f);
            if (row0 + r < M) {
                v = *(const float4*)(A + (size_t)(row0 + r) * K + kt * 32 + c4);
                if (DIVZ) {
                    float invz = 1.f / (zp[(size_t)(row0 + r) * 4 + kt] + 1e-6f);
                    v.x *= invz; v.y *= invz; v.z *= invz; v.w *= invz;
                }
            }
            v.x = tf32r(v.x); v.y = tf32r(v.y); v.z = tf32r(v.z); v.w = tf32r(v.w);
            *(float4*)(A_sh + r * AS + c4) = v;
        }
#pragma unroll
        for (int it = 0; it < 4; ++it) {
            int idx = tid + it * 256;
            int kk = idx >> 5, wc = (idx & 31) << 2;
            size_t go = (size_t)(kt * 32 + kk) * NC + cb + wc;
            *(float4*)(Whi + kk * WS + wc) = *(const float4*)(Wh + go);
            *(float4*)(Wlo + kk * WS + wc) = *(const float4*)(Wl + go);
        }
        __syncthreads();
#pragma unroll
        for (int k8 = 0; k8 < 4; ++k8) {
            int ck = k8 * 8;
            uint32_t a[2][4];
#pragma unroll
            for (int mf = 0; mf < 2; ++mf) {
                int rb = 32 * wm + 16 * mf;
                a[mf][0] = __float_as_uint(A_sh[(rb + g)     * AS + ck + t]);
                a[mf][1] = __float_as_uint(A_sh[(rb + g + 8) * AS + ck + t]);
                a[mf][2] = __float_as_uint(A_sh[(rb + g)     * AS + ck + t + 4]);
                a[mf][3] = __float_as_uint(A_sh[(rb + g + 8) * AS + ck + t + 4]);
            }
#pragma unroll
            for (int nf = 0; nf < 8; ++nf) {
                int nb = 64 * wn + 8 * nf + g;
                uint32_t bh0 = __float_as_uint(Whi[(ck + t)     * WS + nb]);
                uint32_t bh1 = __float_as_uint(Whi[(ck + t + 4) * WS + nb]);
                uint32_t bl0 = __float_as_uint(Wlo[(ck + t)     * WS + nb]);
                uint32_t bl1 = __float_as_uint(Wlo[(ck + t + 4) * WS + nb]);
#pragma unroll
                for (int mf = 0; mf < 2; ++mf) {
                    mma8(acc[mf][nf], a[mf], bl0, bl1);
                    mma8(acc[mf][nf], a[mf], bh0, bh1);
                }
            }
        }
        __syncthreads();
    }
#pragma unroll
    for (int mf = 0; mf < 2; ++mf) {
#pragma unroll
        for (int nf = 0; nf < 8; ++nf) {
            int c  = cb + 64 * wn + 8 * nf + 2 * t;
            int r0 = row0 + 32 * wm + 16 * mf + g;
            float2 v0 = make_float2(acc[mf][nf][0], acc[mf][nf][1]);
            float2 v1 = make_float2(acc[mf][nf][2], acc[mf][nf][3]);
            if (EPI == 2) {
                v0.x = v0.x / (1.f + expf(-v0.x)); v0.y = v0.y / (1.f + expf(-v0.y));
                v1.x = v1.x / (1.f + expf(-v1.x)); v1.y = v1.y / (1.f + expf(-v1.y));
            }
            if (r0 < M) {
                if (EPI == 1) {
                    float2 b = *(const float2*)(bias + c);
                    float2 rr = *(const float2*)(res + (size_t)r0 * NC + c);
                    v0.x += b.x + rr.x; v0.y += b.y + rr.y;
                }
                if (EPI == 3) {
                    float2 rr = *(const float2*)(res + (size_t)r0 * NC + c);
                    v0.x += rr.x; v0.y += rr.y;
                }
                *(float2*)(C + (size_t)r0 * NC + c) = v0;
            }
            int r1 = r0 + 8;
            if (r1 < M) {
                if (EPI == 1) {
                    float2 b = *(const float2*)(bias + c);
                    float2 rr = *(const float2*)(res + (size_t)r1 * NC + c);
                    v1.x += b.x + rr.x; v1.y += b.y + rr.y;
                }
                if (EPI == 3) {
                    float2 rr = *(const float2*)(res + (size_t)r1 * NC + c);
                    v1.x += rr.x; v1.y += rr.y;
                }
                *(float2*)(C + (size_t)r1 * NC + c) = v1;
            }
        }
    }
}

#define GEMM_SMEM ((128 * AS + 2 * 32 * WS) * 4)

template <int EPI, int DIVZ>
__global__ void __launch_bounds__(256, 2) gemm_kernel(
    const float* __restrict__ A, const float* __restrict__ Wh, const float* __restrict__ Wl,
    const float* __restrict__ bias, const float* __restrict__ res, const float* __restrict__ zp,
    float* __restrict__ C, int M, int K, int NC) {
    extern __shared__ float gsh[];
    float* A_sh = gsh;
    float* Whi  = gsh + 128 * AS;
    float* Wlo  = Whi + 32 * WS;
    gemm_body<EPI, DIVZ>(A, Wh, Wl, bias, res, zp, C, M, K, NC,
                         blockIdx.x * 128, blockIdx.y * 128, A_sh, Whi, Wlo);
}

__global__ void __launch_bounds__(256, 2) qkv_kernel(
    const float* __restrict__ A, const float* __restrict__ wh, const float* __restrict__ wl,
    float* __restrict__ Q, float* __restrict__ Ko, float* __restrict__ V, int M) {
    extern __shared__ float gsh[];
    float* A_sh = gsh;
    float* Whi  = gsh + 128 * AS;
    float* Wlo  = Whi + 32 * WS;
    int off = (blockIdx.y == 0) ? OFF_WQ : (blockIdx.y == 1) ? OFF_WK : OFF_WV;
    float* C  = (blockIdx.y == 0) ? Q : (blockIdx.y == 1) ? Ko : V;
    gemm_body<0, 0>(A, wh + off, wl + off, nullptr, nullptr, nullptr, C, M, 128, 128,
                    blockIdx.x * 128, 0, A_sh, Whi, Wlo);
}

// ---------------- fused edge kernel: LN -> Pe GEMM -> score -> scatter -----------------
// edge stream: evict_first policy; Q/K/V gathers: evict_last policy (both via cache_hint).
#define LN_STRIDE 132
__global__ void __launch_bounds__(256, 2) edge_kernel(
    const float* __restrict__ ef, const float* __restrict__ lnw, const float* __restrict__ lnb,
    const float* __restrict__ Weh, const float* __restrict__ Wel,
    const int* __restrict__ src, const int* __restrict__ dst,
    const float* __restrict__ Q, const float* __restrict__ Kv, const float* __restrict__ V,
    float* __restrict__ wV, float* __restrict__ z, int E) {
    extern __shared__ float sh[];
    float* LN_sh = sh;
    float* Whi   = sh + 128 * LN_STRIDE;
    float* Wlo   = Whi + 32 * WS;
    int* s_sh = (int*)(Wlo + 32 * WS);
    int* d_sh = s_sh + 128;

    int tid = threadIdx.x, lane = tid & 31, w = tid >> 5;
    int e0 = blockIdx.x * 128;
    uint64_t pol_stream = mk_stream_policy();
    if (tid < 128) {
        int e = e0 + tid;
        s_sh[tid] = (e < E) ? src[e] : 0;
        d_sh[tid] = (e < E) ? dst[e] : 0;
    }
    float4 lw = *(const float4*)(lnw + 4 * lane);
    float4 lb = *(const float4*)(lnb + 4 * lane);
#pragma unroll
    for (int i = 0; i < 16; i++) {
        int r = w * 16 + i;
        int e = e0 + r;
        float4 v = make_float4(0.f, 0.f, 0.f, 0.f);
        if (e < E) v = ldg_pol(ef + (size_t)e * 128 + 4 * lane, pol_stream);
        float s  = v.x + v.y + v.z + v.w;
        float sq = v.x * v.x + v.y * v.y + v.z * v.z + v.w * v.w;
#pragma unroll
        for (int o = 16; o; o >>= 1) {
            s  += __shfl_xor_sync(0xffffffffu, s,  o);
            sq += __shfl_xor_sync(0xffffffffu, sq, o);
        }
        float mu   = s * (1.f / 128.f);
        float rstd = rsqrtf(sq * (1.f / 128.f) - mu * mu + 1e-5f);
        float4 o4;
        o4.x = tf32r((v.x - mu) * rstd * lw.x + lb.x);
        o4.y = tf32r((v.y - mu) * rstd * lw.y + lb.y);
        o4.z = tf32r((v.z - mu) * rstd * lw.z + lb.z);
        o4.w = tf32r((v.w - mu) * rstd * lw.w + lb.w);
        *(float4*)(LN_sh + r * LN_STRIDE + 4 * lane) = o4;
    }
    __syncthreads();
    int wm = w >> 1, wn = w & 1;
    int g = lane >> 2, t = lane & 3;
    float acc[2][8][4];
#pragma unroll
    for (int mf = 0; mf < 2; mf++)
#pragma unroll
        for (int nf = 0; nf < 8; nf++)
#pragma unroll
            for (int u = 0; u < 4; u++) acc[mf][nf][u] = 0.f;
    for (int kt = 0; kt < 4; ++kt) {
#pragma unroll
        for (int it = 0; it < 4; ++it) {
            int idx = tid + it * 256;
            int kk = idx >> 5, wc = (idx & 31) << 2;
            size_t go = (size_t)(kt * 32 + kk) * 128 + wc;
            *(float4*)(Whi + kk * WS + wc) = *(const float4*)(Weh + go);
            *(float4*)(Wlo + kk * WS + wc) = *(const float4*)(Wel + go);
        }
        __syncthreads();
#pragma unroll
        for (int k8 = 0; k8 < 4; ++k8) {
            int ckA = kt * 32 + k8 * 8;
            int ckW = k8 * 8;
            uint32_t a[2][4];
#pragma unroll
            for (int mf = 0; mf < 2; ++mf) {
                int rb = 32 * wm + 16 * mf;
                a[mf][0] = __float_as_uint(LN_sh[(rb + g)     * LN_STRIDE + ckA + t]);
                a[mf][1] = __float_as_uint(LN_sh[(rb + g + 8) * LN_STRIDE + ckA + t]);
                a[mf][2] = __float_as_uint(LN_sh[(rb + g)     * LN_STRIDE + ckA + t + 4]);
                a[mf][3] = __float_as_uint(LN_sh[(rb + g + 8) * LN_STRIDE + ckA + t + 4]);
            }
#pragma unroll
            for (int nf = 0; nf < 8; ++nf) {
                int nb = 64 * wn + 8 * nf + g;
                uint32_t bh0 = __float_as_uint(Whi[(ckW + t)     * WS + nb]);
                uint32_t bh1 = __float_as_uint(Whi[(ckW + t + 4) * WS + nb]);
                uint32_t bl0 = __float_as_uint(Wlo[(ckW + t)     * WS + nb]);
                uint32_t bl1 = __float_as_uint(Wlo[(ckW + t + 4) * WS + nb]);
#pragma unroll
                for (int mf = 0; mf < 2; ++mf) {
                    mma8(acc[mf][nf], a[mf], bl0, bl1);
                    mma8(acc[mf][nf], a[mf], bh0, bh1);
                }
            }
        }
        __syncthreads();
    }
#pragma unroll
    for (int mf = 0; mf < 2; ++mf) {
#pragma unroll
        for (int nf = 0; nf < 8; ++nf) {
            int r0 = 32 * wm + 16 * mf + g;
            int c  = 64 * wn + 8 * nf + 2 * t;
            *(float2*)(LN_sh + r0 * LN_STRIDE + c)       = make_float2(acc[mf][nf][0], acc[mf][nf][1]);
            *(float2*)(LN_sh + (r0 + 8) * LN_STRIDE + c) = make_float2(acc[mf][nf][2], acc[mf][nf][3]);
        }
    }
    __syncthreads();
    const float inv = 0.17677669529663687f;
    int head = lane >> 3;
    int base = w * 16;
    uint64_t pol = mk_keep_policy();
    int si = s_sh[base], di = d_sh[base];
    float4 kq = ldg_pol(Kv + (size_t)si * 128 + 4 * lane, pol);
    float4 qv = ldg_pol(Q  + (size_t)di * 128 + 4 * lane, pol);
    float4 vv = ldg_pol(V  + (size_t)si * 128 + 4 * lane, pol);
#pragma unroll
    for (int j = 0; j < 16; j++) {
        int e = e0 + base + j;
        float4 kqc = kq, qvc = qv, vvc = vv;
        int dic = di;
        if (j < 15) {
            int sn = s_sh[base + j + 1], dn = d_sh[base + j + 1];
            kq = ldg_pol(Kv + (size_t)sn * 128 + 4 * lane, pol);
            qv = ldg_pol(Q  + (size_t)dn * 128 + 4 * lane, pol);
            vv = ldg_pol(V  + (size_t)sn * 128 + 4 * lane, pol);
            di = dn;
        }
        if (e < E) {
            float4 pe = *(float4*)(LN_sh + (base + j) * LN_STRIDE + 4 * lane);
            float tt = clip5(kqc.x * qvc.x * inv) * pe.x + clip5(kqc.y * qvc.y * inv) * pe.y
                     + clip5(kqc.z * qvc.z * inv) * pe.z + clip5(kqc.w * qvc.w * inv) * pe.w;
            tt += __shfl_xor_sync(0xffffffffu, tt, 1);
            tt += __shfl_xor_sync(0xffffffffu, tt, 2);
            tt += __shfl_xor_sync(0xffffffffu, tt, 4);
            float s = expf(clip5(tt));
            float* dp = wV + (size_t)dic * 128 + 4 * lane;
            red_add_v4(dp, vvc.x * s, vvc.y * s, vvc.z * s, vvc.w * s);
            if ((lane & 7) == 0) red_add_f(z + (size_t)dic * 4 + head, s);
        }
    }
}
#define EDGE_SMEM ((128 * LN_STRIDE + 2 * 32 * WS) * 4 + 2 * 128 * 4)

// ---------------- Set2Set: one block (512 threads) per graph --------------------------
__global__ void __launch_bounds__(512) set2set_kernel(
    const float* __restrict__ nf, const int* __restrict__ gid,
    const float* __restrict__ W_ih, const float* __restrict__ W_hh,
    const float* __restrict__ b_ih, const float* __restrict__ b_hh,
    float* __restrict__ ener, float* __restrict__ out, int N) {
    __shared__ float qs[256], hh[128], cc[128], gates[512], rsh[16 * 128], red[34];
    int tid = threadIdx.x, lane = tid & 31, w = tid >> 5;
    int g = blockIdx.x;
    int lo, hi;
    {
        int a = 0, b = N;
        while (a < b) { int m = (a + b) >> 1; if (gid[m] < g) a = m + 1; else b = m; }
        lo = a;
        b = N;
        while (a < b) { int m = (a + b) >> 1; if (gid[m] < g + 1) a = m + 1; else b = m; }
        hi = a;
    }
    if (tid < 256) qs[tid] = 0.f;
    if (tid < 128) { hh[tid] = 0.f; cc[tid] = 0.f; }
    __syncthreads();

    for (int it = 0; it < 3; ++it) {
        {
            int j = tid;
            float acc = b_ih[j] + b_hh[j];
            const float* wi = W_ih + (size_t)j * 256;
#pragma unroll 8
            for (int k2 = 0; k2 < 256; k2++) acc += qs[k2] * wi[k2];
            const float* whp = W_hh + (size_t)j * 128;
#pragma unroll 8
            for (int k2 = 0; k2 < 128; k2++) acc += hh[k2] * whp[k2];
            gates[j] = acc;
        }
        __syncthreads();
        if (tid < 128) {
            float c = sigm(gates[128 + tid]) * cc[tid] + sigm(gates[tid]) * tanhf(gates[256 + tid]);
            cc[tid] = c;
            hh[tid] = sigm(gates[384 + tid]) * tanhf(c);
        }
        __syncthreads();
        float mloc = -INFINITY;
        float4 h4 = *(float4*)&hh[4 * lane];
        for (int n = lo + w; n < hi; n += 16) {
            float4 a4 = *(const float4*)(nf + (size_t)n * 128 + 4 * lane);
            float t = a4.x * h4.x + a4.y * h4.y + a4.z * h4.z + a4.w * h4.w;
#pragma unroll
            for (int o = 16; o; o >>= 1) t += __shfl_xor_sync(0xffffffffu, t, o);
            if (lane == 0) ener[n] = t;
            mloc = fmaxf(mloc, t);
        }
#pragma unroll
        for (int o = 16; o; o >>= 1) mloc = fmaxf(mloc, __shfl_xor_sync(0xffffffffu, mloc, o));
        if (lane == 0) red[w] = mloc;
        __syncthreads();
        if (tid == 0) {
            float m = -INFINITY;
            for (int i = 0; i < 16; i++) m = fmaxf(m, red[i]);
            red[32] = m;
        }
        __syncthreads();
        float m = red[32];
        float dloc = 0.f;
        for (int n = lo + tid; n < hi; n += 512) dloc += expf(ener[n] - m);
#pragma unroll
        for (int o = 16; o; o >>= 1) dloc += __shfl_xor_sync(0xffffffffu, dloc, o);
        __syncthreads();
        if (lane == 0) red[w] = dloc;
        __syncthreads();
        if (tid == 0) {
            float d = 0.f;
            for (int i = 0; i < 16; i++) d += red[i];
            red[33] = d;
        }
        __syncthreads();
        float invd = 1.f / red[33];
        float4 racc = make_float4(0.f, 0.f, 0.f, 0.f);
        for (int n = lo + w; n < hi; n += 16) {
            float coef = expf(ener[n] - m) * invd;
            float4 a4 = *(const float4*)(nf + (size_t)n * 128 + 4 * lane);
            racc.x += coef * a4.x; racc.y += coef * a4.y;
            racc.z += coef * a4.z; racc.w += coef * a4.w;
        }
        *(float4*)&rsh[w * 128 + 4 * lane] = racc;
        __syncthreads();
        if (tid < 128) {
            float ro = 0.f;
#pragma unroll
            for (int i = 0; i < 16; i++) ro += rsh[i * 128 + tid];
            qs[tid] = hh[tid];
            qs[128 + tid] = ro;
        }
        __syncthreads();
    }
    if (tid < 256) out[(size_t)g * 256 + tid] = qs[tid];
}

// ---------------- launch ----------------
extern "C" void kernel_launch(void* const* d_in, const int* in_sizes, int n_in,
                              void* d_out, int out_size) {
    const float* node = (const float*)d_in[0];
    const float* edge = (const float*)d_in[1];
    const float* Wq = (const float*)d_in[2];
    const float* Wk = (const float*)d_in[3];
    const float* Wv = (const float*)d_in[4];
    const float* We = (const float*)d_in[5];
    const float* Wo = (const float*)d_in[6];
    const float* bo = (const float*)d_in[7];
    const float* W1 = (const float*)d_in[8];
    const float* W2 = (const float*)d_in[9];
    const float* l1nw = (const float*)d_in[10];
    const float* l1nb = (const float*)d_in[11];
    const float* l1ew = (const float*)d_in[12];
    const float* l1eb = (const float*)d_in[13];
    const float* l2w = (const float*)d_in[14];
    const float* l2b = (const float*)d_in[15];
    const float* Wih = (const float*)d_in[16];
    const float* Whh = (const float*)d_in[17];
    const float* bih = (const float*)d_in[18];
    const float* bhh = (const float*)d_in[19];
    const int* src = (const int*)d_in[20];
    const int* dst = (const int*)d_in[21];
    const int* gid = (const int*)d_in[22];

    int N = in_sizes[0] / 128;
    int E = in_sizes[20];
    int G = out_size / 256;

    float *b1, *q, *k, *v, *x, *wv, *z, *t, *en, *wh, *wl;
    cudaGetSymbolAddress((void**)&b1, g_b1);
    cudaGetSymbolAddress((void**)&q,  g_Q);
    cudaGetSymbolAddress((void**)&k,  g_K);
    cudaGetSymbolAddress((void**)&v,  g_V);
    cudaGetSymbolAddress((void**)&x,  g_x);
    cudaGetSymbolAddress((void**)&wv, g_wV);
    cudaGetSymbolAddress((void**)&z,  g_z);
    cudaGetSymbolAddress((void**)&t,  g_t);
    cudaGetSymbolAddress((void**)&en, g_en);
    cudaGetSymbolAddress((void**)&wh, g_wh);
    cudaGetSymbolAddress((void**)&wl, g_wl);

    cudaFuncSetAttribute(edge_kernel, cudaFuncAttributeMaxDynamicSharedMemorySize, EDGE_SMEM);
    cudaFuncSetAttribute(qkv_kernel, cudaFuncAttributeMaxDynamicSharedMemorySize, GEMM_SMEM);
    cudaFuncSetAttribute((const void*)gemm_kernel<1, 1>, cudaFuncAttributeMaxDynamicSharedMemorySize, GEMM_SMEM);
    cudaFuncSetAttribute((const void*)gemm_kernel<2, 0>, cudaFuncAttributeMaxDynamicSharedMemorySize, GEMM_SMEM);
    cudaFuncSetAttribute((const void*)gemm_kernel<3, 0>, cudaFuncAttributeMaxDynamicSharedMemorySize, GEMM_SMEM);

    int gnodes = (N + 127) / 128;
    int prep_threads = N * 33 + W_TOTAL4;

    prep_kernel<<<(prep_threads + 255) / 256, 256>>>((float4*)wv, (float4*)z, N * 32, N,
                                                     Wq, Wk, Wv, We, Wo, W1, W2, wh, wl);
    ln_kernel<<<(N + 7) / 8, 256>>>(node, b1, l1nw, l1nb, N);
    qkv_kernel<<<dim3(gnodes, 3), 256, GEMM_SMEM>>>(b1, wh, wl, q, k, v, N);
    edge_kernel<<<(E + 127) / 128, 256, EDGE_SMEM>>>(edge, l1ew, l1eb, wh + OFF_WE, wl + OFF_WE,
                                                     src, dst, q, k, v, wv, z, E);
    gemm_kernel<1, 1><<<dim3(gnodes, 1), 256, GEMM_SMEM>>>(wv, wh + OFF_WO, wl + OFF_WO,
                                                           bo, node, z, x, N, 128, 128);
    ln_kernel<<<(N + 7) / 8, 256>>>(x, q, l2w, l2b, N);
    gemm_kernel<2, 0><<<dim3(gnodes, 2), 256, GEMM_SMEM>>>(q, wh + OFF_W1, wl + OFF_W1,
                                                           nullptr, nullptr, nullptr, t, N, 128, 256);
    gemm_kernel<3, 0><<<dim3(gnodes, 1), 256, GEMM_SMEM>>>(t, wh + OFF_W2, wl + OFF_W2,
                                                           nullptr, x, nullptr, k, N, 256, 128);
    set2set_kernel<<<G, 512>>>(k, gid, Wih, Whh, bih, bhh, en, (float*)d_out, N);
}